// round 1
// baseline (speedup 1.0000x reference)
#include <cuda_runtime.h>
#include <cuda_bf16.h>
#include <math.h>

// Problem constants
#define BB 64
#define TT 256
#define CC 384
#define HH 6
#define HS 64
#define MM (BB * TT)          // 16384
#define NQKV (3 * CC)         // 1152
#define CF (4 * CC)           // 1536

// ---------------- scratch (static __device__, no allocs) ----------------
__device__ float g_h[MM * CC];        // ln output (reused for ln1 and ln2)
__device__ float g_qkv[MM * NQKV];    // packed Q|K|V, row = token, col = h*HS+d
__device__ float g_o[MM * CC];        // attention output (head-concat)
__device__ float g_x1[MM * CC];       // first residual
__device__ float g_f1[MM * CF];       // FFN hidden
__device__ float g_Wqkv[CC * NQKV];   // packed QKV weight [K=C, N=1152]
__device__ float g_bqkv[NQKV];

// ---------------- f32x2 helpers (paired fp32 datapath) ----------------
__device__ __forceinline__ unsigned long long pk2(float lo, float hi) {
    unsigned long long r;
    asm("mov.b64 %0, {%1, %2};" : "=l"(r) : "f"(lo), "f"(hi));
    return r;
}
__device__ __forceinline__ float2 up2(unsigned long long v) {
    float2 r;
    asm("mov.b64 {%0, %1}, %2;" : "=f"(r.x), "=f"(r.y) : "l"(v));
    return r;
}
__device__ __forceinline__ unsigned long long ffma2(unsigned long long a,
                                                    unsigned long long b,
                                                    unsigned long long c) {
    unsigned long long d;
    asm("fma.rn.f32x2 %0, %1, %2, %3;" : "=l"(d) : "l"(a), "l"(b), "l"(c));
    return d;
}
__device__ __forceinline__ unsigned long long fmul2(unsigned long long a,
                                                    unsigned long long b) {
    unsigned long long d;
    asm("mul.rn.f32x2 %0, %1, %2;" : "=l"(d) : "l"(a), "l"(b));
    return d;
}

// ---------------- pack QKV weights: Wq/Wk/Wv [H,C,HS] -> [C, 1152] ----------------
__global__ void pack_qkv_kernel(const float* __restrict__ Wq, const float* __restrict__ Wk,
                                const float* __restrict__ Wv, const float* __restrict__ bq,
                                const float* __restrict__ bk, const float* __restrict__ bv) {
    int idx = blockIdx.x * blockDim.x + threadIdx.x;
    if (idx < CC * NQKV) {
        int n = idx % NQKV;
        int c = idx / NQKV;
        int sel = n / CC;
        int nn = n % CC;                      // = h*HS + d
        const float* src = (sel == 0) ? Wq : (sel == 1) ? Wk : Wv;
        g_Wqkv[idx] = src[(nn / HS) * (CC * HS) + c * HS + (nn % HS)];
    }
    if (idx < NQKV) {
        int sel = idx / CC;
        int nn = idx % CC;
        const float* sb = (sel == 0) ? bq : (sel == 1) ? bk : bv;
        g_bqkv[idx] = sb[nn];
    }
}

// ---------------- LayerNorm: one block per row (C = 384, 128 threads) ----------------
__global__ __launch_bounds__(128) void ln_kernel(const float* __restrict__ x,
                                                 const float* __restrict__ w,
                                                 const float* __restrict__ b,
                                                 float* __restrict__ y) {
    int row = blockIdx.x;
    const float* xr = x + (size_t)row * CC;
    int tid = threadIdx.x;
    float v0 = xr[tid], v1 = xr[tid + 128], v2 = xr[tid + 256];
    float s = v0 + v1 + v2;
    float ss = v0 * v0 + v1 * v1 + v2 * v2;
    __shared__ float red[8];
    #pragma unroll
    for (int o = 16; o > 0; o >>= 1) {
        s += __shfl_down_sync(0xffffffffu, s, o);
        ss += __shfl_down_sync(0xffffffffu, ss, o);
    }
    int wid = tid >> 5, lid = tid & 31;
    if (lid == 0) { red[wid] = s; red[4 + wid] = ss; }
    __syncthreads();
    if (tid == 0) {
        float S = red[0] + red[1] + red[2] + red[3];
        float SS = red[4] + red[5] + red[6] + red[7];
        float mean = S * (1.0f / CC);
        float var = SS * (1.0f / CC) - mean * mean;
        red[0] = mean;
        red[1] = rsqrtf(var + 1e-5f);
    }
    __syncthreads();
    float mean = red[0], inv = red[1];
    float* yr = y + (size_t)row * CC;
    yr[tid]       = (v0 - mean) * inv * w[tid]       + b[tid];
    yr[tid + 128] = (v1 - mean) * inv * w[tid + 128] + b[tid + 128];
    yr[tid + 256] = (v2 - mean) * inv * w[tid + 256] + b[tid + 256];
}

// ---------------- GEMM: C = A[M,K] @ B[K,N] + bias (+residual | gelu) ----------------
// 128x128x8 tiles, 256 threads, 8x8 per thread as 8x(4 f32x2).
// MODE 0: +bias   MODE 1: +bias+residual   MODE 2: gelu(+bias)
template <int MODE>
__global__ __launch_bounds__(256) void gemm_kernel(const float* __restrict__ A,
                                                   const float* __restrict__ Bw,
                                                   const float* __restrict__ bias,
                                                   const float* __restrict__ Rres,
                                                   float* __restrict__ Cout,
                                                   int M, int N, int K) {
    __shared__ float As[8][128];
    __shared__ float Bs[8][128];
    int tid = threadIdx.x;
    int row0 = blockIdx.y * 128;
    int col0 = blockIdx.x * 128;

    int aRow = tid >> 1;          // 0..127
    int aK = (tid & 1) * 4;       // 0 or 4
    int bRow = tid >> 5;          // 0..7
    int bCol = (tid & 31) * 4;

    int ty = tid >> 4, tx = tid & 15;

    unsigned long long acc[8][4];
    #pragma unroll
    for (int i = 0; i < 8; i++)
        #pragma unroll
        for (int j = 0; j < 4; j++) acc[i][j] = 0ull;

    const float* Aptr = A + (size_t)(row0 + aRow) * K + aK;
    const float* Bptr = Bw + (size_t)bRow * N + col0 + bCol;

    for (int k0 = 0; k0 < K; k0 += 8) {
        float4 av = *(const float4*)(Aptr + k0);
        float4 bv = *(const float4*)(Bptr + (size_t)k0 * N);
        As[aK + 0][aRow] = av.x;
        As[aK + 1][aRow] = av.y;
        As[aK + 2][aRow] = av.z;
        As[aK + 3][aRow] = av.w;
        *(float4*)&Bs[bRow][bCol] = bv;
        __syncthreads();
        #pragma unroll
        for (int kk = 0; kk < 8; kk++) {
            float4 a0 = *(const float4*)&As[kk][ty * 8];
            float4 a1 = *(const float4*)&As[kk][ty * 8 + 4];
            ulonglong2 b0 = *(const ulonglong2*)&Bs[kk][tx * 8];
            ulonglong2 b1 = *(const ulonglong2*)&Bs[kk][tx * 8 + 4];
            unsigned long long bp0 = b0.x, bp1 = b0.y, bp2 = b1.x, bp3 = b1.y;
            float aa[8] = {a0.x, a0.y, a0.z, a0.w, a1.x, a1.y, a1.z, a1.w};
            #pragma unroll
            for (int i = 0; i < 8; i++) {
                unsigned long long ap = pk2(aa[i], aa[i]);
                acc[i][0] = ffma2(ap, bp0, acc[i][0]);
                acc[i][1] = ffma2(ap, bp1, acc[i][1]);
                acc[i][2] = ffma2(ap, bp2, acc[i][2]);
                acc[i][3] = ffma2(ap, bp3, acc[i][3]);
            }
        }
        __syncthreads();
    }

    int crow = row0 + ty * 8;
    int ccol = col0 + tx * 8;
    #pragma unroll
    for (int i = 0; i < 8; i++) {
        float out[8];
        #pragma unroll
        for (int j = 0; j < 4; j++) {
            float2 v = up2(acc[i][j]);
            out[2 * j] = v.x;
            out[2 * j + 1] = v.y;
        }
        size_t rbase = (size_t)(crow + i) * N + ccol;
        #pragma unroll
        for (int j = 0; j < 8; j++) {
            float v = out[j] + bias[ccol + j];
            if (MODE == 1) v += Rres[rbase + j];
            if (MODE == 2) v = 0.5f * v * (1.0f + erff(v * 0.70710678118654752f));
            out[j] = v;
        }
        *(float4*)&Cout[rbase] = make_float4(out[0], out[1], out[2], out[3]);
        *(float4*)&Cout[rbase + 4] = make_float4(out[4], out[5], out[6], out[7]);
    }
}

// ---------------- causal attention: one CTA per (b,h), K/V in smem ----------------
// qkv layout: [M, 1152], Q at col h*64, K at 384+h*64, V at 768+h*64.
__global__ __launch_bounds__(256) void attn_kernel(const float* __restrict__ qkv,
                                                   float* __restrict__ o) {
    extern __shared__ float sm[];
    float* Ks = sm;                 // [256][64]
    float* Vs = sm + TT * HS;       // [256][64]
    int bh = blockIdx.x;
    int b = bh / HH, h = bh % HH;
    size_t base = (size_t)b * TT * NQKV + h * HS;
    int tid = threadIdx.x;

    for (int i = tid; i < TT * HS / 4; i += 256) {
        int s = i >> 4;
        int j = (i & 15) << 2;
        *(float4*)&Ks[s * HS + j] = *(const float4*)&qkv[base + (size_t)s * NQKV + CC + j];
        *(float4*)&Vs[s * HS + j] = *(const float4*)&qkv[base + (size_t)s * NQKV + 2 * CC + j];
    }
    __syncthreads();

    int t = tid;
    unsigned long long q2[32];
    #pragma unroll
    for (int j = 0; j < 16; j++) {
        ulonglong2 v = *(const ulonglong2*)&qkv[base + (size_t)t * NQKV + 4 * j];
        q2[2 * j] = v.x;
        q2[2 * j + 1] = v.y;
    }
    unsigned long long acc2[32];
    #pragma unroll
    for (int j = 0; j < 32; j++) acc2[j] = 0ull;

    float m = -1e30f, l = 0.0f;
    for (int s = 0; s <= t; s++) {
        const ulonglong2* kp = (const ulonglong2*)&Ks[s * HS];
        unsigned long long d2 = 0ull;
        #pragma unroll
        for (int j = 0; j < 16; j++) {
            ulonglong2 kk = kp[j];
            d2 = ffma2(q2[2 * j], kk.x, d2);
            d2 = ffma2(q2[2 * j + 1], kk.y, d2);
        }
        float2 df = up2(d2);
        float dot = (df.x + df.y) * 0.125f;   // HS^-0.5
        float mn = fmaxf(m, dot);
        float a = __expf(m - mn);
        float p = __expf(dot - mn);
        l = l * a + p;
        unsigned long long a2 = pk2(a, a);
        unsigned long long p2 = pk2(p, p);
        const ulonglong2* vp = (const ulonglong2*)&Vs[s * HS];
        #pragma unroll
        for (int j = 0; j < 16; j++) {
            ulonglong2 vv = vp[j];
            acc2[2 * j]     = ffma2(acc2[2 * j],     a2, fmul2(p2, vv.x));
            acc2[2 * j + 1] = ffma2(acc2[2 * j + 1], a2, fmul2(p2, vv.y));
        }
        m = mn;
    }
    float invl = 1.0f / l;
    float* op = o + (size_t)(b * TT + t) * CC + h * HS;
    #pragma unroll
    for (int j = 0; j < 16; j++) {
        float2 v0 = up2(acc2[2 * j]);
        float2 v1 = up2(acc2[2 * j + 1]);
        *(float4*)&op[4 * j] = make_float4(v0.x * invl, v0.y * invl, v1.x * invl, v1.y * invl);
    }
}

// ---------------- launch ----------------
extern "C" void kernel_launch(void* const* d_in, const int* in_sizes, int n_in,
                              void* d_out, int out_size) {
    const float* x     = (const float*)d_in[0];
    const float* ln1w  = (const float*)d_in[1];
    const float* ln1b  = (const float*)d_in[2];
    const float* Wq    = (const float*)d_in[3];
    const float* bq    = (const float*)d_in[4];
    const float* Wk    = (const float*)d_in[5];
    const float* bk    = (const float*)d_in[6];
    const float* Wv    = (const float*)d_in[7];
    const float* bv    = (const float*)d_in[8];
    const float* Wproj = (const float*)d_in[9];
    const float* bproj = (const float*)d_in[10];
    const float* ln2w  = (const float*)d_in[11];
    const float* ln2b  = (const float*)d_in[12];
    const float* W1    = (const float*)d_in[13];
    const float* b1    = (const float*)d_in[14];
    const float* W2    = (const float*)d_in[15];
    const float* b2    = (const float*)d_in[16];
    float* out = (float*)d_out;

    float *h, *qkv, *o, *x1, *f1, *wqkv, *bqkv;
    cudaGetSymbolAddress((void**)&h, g_h);
    cudaGetSymbolAddress((void**)&qkv, g_qkv);
    cudaGetSymbolAddress((void**)&o, g_o);
    cudaGetSymbolAddress((void**)&x1, g_x1);
    cudaGetSymbolAddress((void**)&f1, g_f1);
    cudaGetSymbolAddress((void**)&wqkv, g_Wqkv);
    cudaGetSymbolAddress((void**)&bqkv, g_bqkv);

    cudaFuncSetAttribute(attn_kernel, cudaFuncAttributeMaxDynamicSharedMemorySize,
                         2 * TT * HS * (int)sizeof(float));

    // 1. pack QKV weights/bias
    pack_qkv_kernel<<<(CC * NQKV + 255) / 256, 256>>>(Wq, Wk, Wv, bq, bk, bv);
    // 2. LN1
    ln_kernel<<<MM, 128>>>(x, ln1w, ln1b, h);
    // 3. QKV GEMM: [16384,384] x [384,1152]
    gemm_kernel<0><<<dim3(NQKV / 128, MM / 128), 256>>>(h, wqkv, bqkv, nullptr, qkv, MM, NQKV, CC);
    // 4. causal attention
    attn_kernel<<<BB * HH, 256, 2 * TT * HS * (int)sizeof(float)>>>(qkv, o);
    // 5. proj + residual: x1 = x + o@Wproj + bproj
    gemm_kernel<1><<<dim3(CC / 128, MM / 128), 256>>>(o, Wproj, bproj, x, x1, MM, CC, CC);
    // 6. LN2
    ln_kernel<<<MM, 128>>>(x1, ln2w, ln2b, h);
    // 7. FFN1 + exact GELU: [16384,384] x [384,1536]
    gemm_kernel<2><<<dim3(CF / 128, MM / 128), 256>>>(h, W1, b1, nullptr, f1, MM, CF, CC);
    // 8. FFN2 + residual: out = x1 + f1@W2 + b2
    gemm_kernel<1><<<dim3(CC / 128, MM / 128), 256>>>(f1, W2, b2, x1, out, MM, CC, CF);
}

// round 4
// speedup vs baseline: 2.0147x; 2.0147x over previous
#include <cuda_runtime.h>
#include <cuda_bf16.h>
#include <math.h>
#include <cstdint>

// Problem constants
#define BB 64
#define TT 256
#define CC 384
#define HH 6
#define HS 64
#define MM (BB * TT)          // 16384
#define NQKV (3 * CC)         // 1152
#define CF (4 * CC)           // 1536

// ---------------- scratch (static __device__, no allocs) ----------------
__device__ float g_h[MM * CC];        // ln output (reused for ln1 and ln2)
__device__ float g_qkv[MM * NQKV];    // packed Q|K|V, row = token, col = h*HS+d
__device__ float g_o[MM * CC];        // attention output (head-concat)
__device__ float g_x1[MM * CC];       // first residual
__device__ float g_f1[MM * CF];       // FFN hidden
// transposed (N-major, K-contig) tf32-rounded weights
__device__ float g_WqkvT[NQKV * CC];
__device__ float g_WprojT[CC * CC];
__device__ float g_W1T[CF * CC];
__device__ float g_W2T[CC * CF];
__device__ float g_bqkv[NQKV];

__device__ __forceinline__ float to_tf32(float x) {
    float r;
    asm("cvt.rna.tf32.f32 %0, %1;" : "=f"(r) : "f"(x));
    return r;
}

// ---------------- weight pack kernels ----------------
__global__ void transpose_w(const float* __restrict__ src, float* __restrict__ dst,
                            int K, int N) {
    int i = blockIdx.x * 256 + threadIdx.x;
    if (i < K * N) {
        int n = i / K, k = i % K;
        dst[i] = to_tf32(src[(size_t)k * N + n]);
    }
}

__global__ void pack_qkv_t(const float* __restrict__ Wq, const float* __restrict__ Wk,
                           const float* __restrict__ Wv, const float* __restrict__ bq,
                           const float* __restrict__ bk, const float* __restrict__ bv) {
    int i = blockIdx.x * 256 + threadIdx.x;
    if (i < NQKV * CC) {
        int n = i / CC;                  // output feature 0..1151
        int k = i % CC;
        int s2 = n / CC;                 // 0,1,2 selects Q/K/V
        int nn = n % CC;                 // h*HS + d
        const float* src = (s2 == 0) ? Wq : (s2 == 1) ? Wk : Wv;
        g_WqkvT[i] = to_tf32(src[(nn / HS) * (CC * HS) + k * HS + (nn % HS)]);
    }
    if (i < NQKV) {
        int s2 = i / CC;
        int nn = i % CC;
        const float* sb = (s2 == 0) ? bq : (s2 == 1) ? bk : bv;
        g_bqkv[i] = sb[nn];
    }
}

// ---------------- LayerNorm ----------------
__global__ __launch_bounds__(128) void ln_kernel(const float* __restrict__ x,
                                                 const float* __restrict__ w,
                                                 const float* __restrict__ b,
                                                 float* __restrict__ y) {
    int row = blockIdx.x;
    const float* xr = x + (size_t)row * CC;
    int tid = threadIdx.x;
    float v0 = xr[tid], v1 = xr[tid + 128], v2 = xr[tid + 256];
    float s = v0 + v1 + v2;
    float ss = v0 * v0 + v1 * v1 + v2 * v2;
    __shared__ float red[8];
    #pragma unroll
    for (int o = 16; o > 0; o >>= 1) {
        s += __shfl_down_sync(0xffffffffu, s, o);
        ss += __shfl_down_sync(0xffffffffu, ss, o);
    }
    int wid = tid >> 5, lid = tid & 31;
    if (lid == 0) { red[wid] = s; red[4 + wid] = ss; }
    __syncthreads();
    if (tid == 0) {
        float S = red[0] + red[1] + red[2] + red[3];
        float SS = red[4] + red[5] + red[6] + red[7];
        float mean = S * (1.0f / CC);
        float var = SS * (1.0f / CC) - mean * mean;
        red[0] = mean;
        red[1] = rsqrtf(var + 1e-5f);
    }
    __syncthreads();
    float mean = red[0], inv = red[1];
    float* yr = y + (size_t)row * CC;
    yr[tid]       = (v0 - mean) * inv * w[tid]       + b[tid];
    yr[tid + 128] = (v1 - mean) * inv * w[tid + 128] + b[tid + 128];
    yr[tid + 256] = (v2 - mean) * inv * w[tid + 256] + b[tid + 256];
}

// ---------------- tf32 mma.sync GEMM ----------------
// C[M,N] = A[M,K] @ Bt[N,K]^T + bias ; MODE 0 bias, 1 bias+residual, 2 gelu(bias)
// CTA tile 128x128, 8 warps (2M x 4N), warp tile 64x32, m16n8k8 tf32.
#define PAD 36

__device__ __forceinline__ void mma_tf32_16n8k8(float* c, const uint32_t* a, const uint32_t* b) {
    asm volatile(
        "mma.sync.aligned.m16n8k8.row.col.f32.tf32.tf32.f32 "
        "{%0,%1,%2,%3}, {%4,%5,%6,%7}, {%8,%9}, {%0,%1,%2,%3};"
        : "+f"(c[0]), "+f"(c[1]), "+f"(c[2]), "+f"(c[3])
        : "r"(a[0]), "r"(a[1]), "r"(a[2]), "r"(a[3]), "r"(b[0]), "r"(b[1]));
}

template <int MODE>
__global__ __launch_bounds__(256) void mma_gemm(const float* __restrict__ A,
                                                const float* __restrict__ Bt,
                                                const float* __restrict__ bias,
                                                const float* __restrict__ Rres,
                                                float* __restrict__ Cout,
                                                int M, int N, int K) {
    __shared__ float sA[128 * PAD];
    __shared__ float sB[128 * PAD];
    int tid = threadIdx.x;
    int lane = tid & 31, wid = tid >> 5;
    int warpM = wid & 1, warpN = wid >> 1;
    int g = lane >> 2, tg = lane & 3;
    int row0 = blockIdx.y * 128, col0 = blockIdx.x * 128;

    // gmem load assignment: 16 floats (4xfloat4) per thread for A and B
    int ldRow = tid >> 1;
    int ldCol = (tid & 1) * 16;
    const float* Ap = A + (size_t)(row0 + ldRow) * K + ldCol;
    const float* Bp = Bt + (size_t)(col0 + ldRow) * K + ldCol;

    float4 av[4], bv[4];
    #pragma unroll
    for (int j = 0; j < 4; j++) {
        av[j] = *(const float4*)(Ap + j * 4);
        bv[j] = *(const float4*)(Bp + j * 4);
    }

    float acc[4][4][4];
    #pragma unroll
    for (int mi = 0; mi < 4; mi++)
        #pragma unroll
        for (int ni = 0; ni < 4; ni++)
            #pragma unroll
            for (int r = 0; r < 4; r++) acc[mi][ni][r] = 0.0f;

    int nk = K / 32;
    for (int c = 0; c < nk; c++) {
        // store current chunk to smem (tf32-round activations; weights pre-rounded)
        #pragma unroll
        for (int j = 0; j < 4; j++) {
            float4 a = av[j], b = bv[j];
            a.x = to_tf32(a.x); a.y = to_tf32(a.y); a.z = to_tf32(a.z); a.w = to_tf32(a.w);
            *(float4*)&sA[ldRow * PAD + ldCol + j * 4] = a;
            *(float4*)&sB[ldRow * PAD + ldCol + j * 4] = b;
        }
        __syncthreads();
        // prefetch next chunk (overlaps with compute)
        if (c + 1 < nk) {
            #pragma unroll
            for (int j = 0; j < 4; j++) {
                av[j] = *(const float4*)(Ap + (c + 1) * 32 + j * 4);
                bv[j] = *(const float4*)(Bp + (c + 1) * 32 + j * 4);
            }
        }
        // compute: 4 k-steps of 8
        #pragma unroll
        for (int ks = 0; ks < 4; ks++) {
            int kb = ks * 8;
            uint32_t afr[4][4], bfr[4][2];
            #pragma unroll
            for (int mi = 0; mi < 4; mi++) {
                int m0 = warpM * 64 + mi * 16;
                afr[mi][0] = __float_as_uint(sA[(m0 + g) * PAD + kb + tg]);
                afr[mi][1] = __float_as_uint(sA[(m0 + g + 8) * PAD + kb + tg]);
                afr[mi][2] = __float_as_uint(sA[(m0 + g) * PAD + kb + tg + 4]);
                afr[mi][3] = __float_as_uint(sA[(m0 + g + 8) * PAD + kb + tg + 4]);
            }
            #pragma unroll
            for (int ni = 0; ni < 4; ni++) {
                int n0 = warpN * 32 + ni * 8;
                bfr[ni][0] = __float_as_uint(sB[(n0 + g) * PAD + kb + tg]);
                bfr[ni][1] = __float_as_uint(sB[(n0 + g) * PAD + kb + tg + 4]);
            }
            #pragma unroll
            for (int mi = 0; mi < 4; mi++)
                #pragma unroll
                for (int ni = 0; ni < 4; ni++)
                    mma_tf32_16n8k8(acc[mi][ni], afr[mi], bfr[ni]);
        }
        __syncthreads();
    }

    // epilogue
    #pragma unroll
    for (int mi = 0; mi < 4; mi++) {
        #pragma unroll
        for (int ni = 0; ni < 4; ni++) {
            int rA = row0 + warpM * 64 + mi * 16 + g;
            int cA = col0 + warpN * 32 + ni * 8 + tg * 2;
            float b0 = bias[cA], b1 = bias[cA + 1];
            #pragma unroll
            for (int half = 0; half < 2; half++) {
                int r = rA + half * 8;
                float o0 = acc[mi][ni][half * 2 + 0] + b0;
                float o1 = acc[mi][ni][half * 2 + 1] + b1;
                size_t idx = (size_t)r * N + cA;
                if (MODE == 1) {
                    const float2 rr = *(const float2*)&Rres[idx];
                    o0 += rr.x; o1 += rr.y;
                }
                if (MODE == 2) {
                    o0 = 0.5f * o0 * (1.0f + erff(o0 * 0.70710678118654752f));
                    o1 = 0.5f * o1 * (1.0f + erff(o1 * 0.70710678118654752f));
                }
                *(float2*)&Cout[idx] = make_float2(o0, o1);
            }
        }
    }
}

// ---------------- f32x2 helpers for attention ----------------
__device__ __forceinline__ unsigned long long pk2(float lo, float hi) {
    unsigned long long r;
    asm("mov.b64 %0, {%1, %2};" : "=l"(r) : "f"(lo), "f"(hi));
    return r;
}
__device__ __forceinline__ float2 up2(unsigned long long v) {
    float2 r;
    asm("mov.b64 {%0, %1}, %2;" : "=f"(r.x), "=f"(r.y) : "l"(v));
    return r;
}
__device__ __forceinline__ unsigned long long ffma2(unsigned long long a,
                                                    unsigned long long b,
                                                    unsigned long long c) {
    unsigned long long d;
    asm("fma.rn.f32x2 %0, %1, %2, %3;" : "=l"(d) : "l"(a), "l"(b), "l"(c));
    return d;
}
__device__ __forceinline__ unsigned long long fmul2(unsigned long long a,
                                                    unsigned long long b) {
    unsigned long long d;
    asm("mul.rn.f32x2 %0, %1, %2;" : "=l"(d) : "l"(a), "l"(b));
    return d;
}

// ---------------- causal attention: one CTA per (b,h), K/V in smem ----------------
__global__ __launch_bounds__(256) void attn_kernel(const float* __restrict__ qkv,
                                                   float* __restrict__ o) {
    extern __shared__ float sm[];
    float* Ks = sm;
    float* Vs = sm + TT * HS;
    int bh = blockIdx.x;
    int b = bh / HH, h = bh % HH;
    size_t base = (size_t)b * TT * NQKV + h * HS;
    int tid = threadIdx.x;

    for (int i = tid; i < TT * HS / 4; i += 256) {
        int s = i >> 4;
        int j = (i & 15) << 2;
        *(float4*)&Ks[s * HS + j] = *(const float4*)&qkv[base + (size_t)s * NQKV + CC + j];
        *(float4*)&Vs[s * HS + j] = *(const float4*)&qkv[base + (size_t)s * NQKV + 2 * CC + j];
    }
    __syncthreads();

    int t = tid;
    unsigned long long q2[32];
    #pragma unroll
    for (int j = 0; j < 16; j++) {
        ulonglong2 v = *(const ulonglong2*)&qkv[base + (size_t)t * NQKV + 4 * j];
        q2[2 * j] = v.x;
        q2[2 * j + 1] = v.y;
    }
    unsigned long long acc2[32];
    #pragma unroll
    for (int j = 0; j < 32; j++) acc2[j] = 0ull;

    float m = -1e30f, l = 0.0f;
    for (int s = 0; s <= t; s++) {
        const ulonglong2* kp = (const ulonglong2*)&Ks[s * HS];
        unsigned long long d2 = 0ull;
        #pragma unroll
        for (int j = 0; j < 16; j++) {
            ulonglong2 kk = kp[j];
            d2 = ffma2(q2[2 * j], kk.x, d2);
            d2 = ffma2(q2[2 * j + 1], kk.y, d2);
        }
        float2 df = up2(d2);
        float dot = (df.x + df.y) * 0.125f;
        float mn = fmaxf(m, dot);
        float a = __expf(m - mn);
        float p = __expf(dot - mn);
        l = l * a + p;
        unsigned long long a2 = pk2(a, a);
        unsigned long long p2 = pk2(p, p);
        const ulonglong2* vp = (const ulonglong2*)&Vs[s * HS];
        #pragma unroll
        for (int j = 0; j < 16; j++) {
            ulonglong2 vv = vp[j];
            acc2[2 * j]     = ffma2(acc2[2 * j],     a2, fmul2(p2, vv.x));
            acc2[2 * j + 1] = ffma2(acc2[2 * j + 1], a2, fmul2(p2, vv.y));
        }
        m = mn;
    }
    float invl = 1.0f / l;
    float* op = o + (size_t)(b * TT + t) * CC + h * HS;
    #pragma unroll
    for (int j = 0; j < 16; j++) {
        float2 v0 = up2(acc2[2 * j]);
        float2 v1 = up2(acc2[2 * j + 1]);
        *(float4*)&op[4 * j] = make_float4(v0.x * invl, v0.y * invl, v1.x * invl, v1.y * invl);
    }
}

// ---------------- launch ----------------
extern "C" void kernel_launch(void* const* d_in, const int* in_sizes, int n_in,
                              void* d_out, int out_size) {
    const float* x     = (const float*)d_in[0];
    const float* ln1w  = (const float*)d_in[1];
    const float* ln1b  = (const float*)d_in[2];
    const float* Wq    = (const float*)d_in[3];
    const float* bq    = (const float*)d_in[4];
    const float* Wk    = (const float*)d_in[5];
    const float* bk    = (const float*)d_in[6];
    const float* Wv    = (const float*)d_in[7];
    const float* bv    = (const float*)d_in[8];
    const float* Wproj = (const float*)d_in[9];
    const float* bproj = (const float*)d_in[10];
    const float* ln2w  = (const float*)d_in[11];
    const float* ln2b  = (const float*)d_in[12];
    const float* W1    = (const float*)d_in[13];
    const float* b1    = (const float*)d_in[14];
    const float* W2    = (const float*)d_in[15];
    const float* b2    = (const float*)d_in[16];
    float* out = (float*)d_out;

    float *h, *qkv, *o, *x1, *f1, *wqkvT, *wprojT, *w1T, *w2T, *bqkv;
    cudaGetSymbolAddress((void**)&h, g_h);
    cudaGetSymbolAddress((void**)&qkv, g_qkv);
    cudaGetSymbolAddress((void**)&o, g_o);
    cudaGetSymbolAddress((void**)&x1, g_x1);
    cudaGetSymbolAddress((void**)&f1, g_f1);
    cudaGetSymbolAddress((void**)&wqkvT, g_WqkvT);
    cudaGetSymbolAddress((void**)&wprojT, g_WprojT);
    cudaGetSymbolAddress((void**)&w1T, g_W1T);
    cudaGetSymbolAddress((void**)&w2T, g_W2T);
    cudaGetSymbolAddress((void**)&bqkv, g_bqkv);

    cudaFuncSetAttribute(attn_kernel, cudaFuncAttributeMaxDynamicSharedMemorySize,
                         2 * TT * HS * (int)sizeof(float));

    // weight packing (tf32-rounded, transposed to [N,K])
    pack_qkv_t<<<(NQKV * CC + 255) / 256, 256>>>(Wq, Wk, Wv, bq, bk, bv);
    transpose_w<<<(CC * CC + 255) / 256, 256>>>(Wproj, wprojT, CC, CC);
    transpose_w<<<(CF * CC + 255) / 256, 256>>>(W1, w1T, CC, CF);
    transpose_w<<<(CC * CF + 255) / 256, 256>>>(W2, w2T, CF, CC);

    // LN1
    ln_kernel<<<MM, 128>>>(x, ln1w, ln1b, h);
    // QKV GEMM
    mma_gemm<0><<<dim3(NQKV / 128, MM / 128), 256>>>(h, wqkvT, bqkv, nullptr, qkv, MM, NQKV, CC);
    // attention
    attn_kernel<<<BB * HH, 256, 2 * TT * HS * (int)sizeof(float)>>>(qkv, o);
    // proj + residual
    mma_gemm<1><<<dim3(CC / 128, MM / 128), 256>>>(o, wprojT, bproj, x, x1, MM, CC, CC);
    // LN2
    ln_kernel<<<MM, 128>>>(x1, ln2w, ln2b, h);
    // FFN1 + GELU
    mma_gemm<2><<<dim3(CF / 128, MM / 128), 256>>>(h, w1T, b1, nullptr, f1, MM, CF, CC);
    // FFN2 + residual
    mma_gemm<1><<<dim3(CC / 128, MM / 128), 256>>>(f1, w2T, b2, x1, out, MM, CC, CF);
}

// round 5
// speedup vs baseline: 3.2997x; 1.6378x over previous
#include <cuda_runtime.h>
#include <cuda_fp16.h>
#include <math.h>
#include <cstdint>

// Problem constants
#define BB 64
#define TT 256
#define CC 384
#define HH 6
#define HS 64
#define MM (BB * TT)          // 16384
#define NQKV (3 * CC)         // 1152
#define CF (4 * CC)           // 1536

// ---------------- scratch (static __device__, no allocs) ----------------
__device__ __half g_h[MM * CC];       // ln output (half, GEMM A input)
__device__ float  g_qkv[MM * NQKV];   // packed Q|K|V (f32 for attention)
__device__ __half g_o[MM * CC];       // attention output (half)
__device__ float  g_x1[MM * CC];      // first residual (f32)
__device__ __half g_f1[MM * CF];      // FFN hidden (half)
// transposed (N-major, K-contig) fp16 weights
__device__ __half g_WqkvT[NQKV * CC];
__device__ __half g_WprojT[CC * CC];
__device__ __half g_W1T[CF * CC];
__device__ __half g_W2T[CC * CF];
__device__ float  g_bqkv[NQKV];

__device__ __forceinline__ uint32_t smem_u32(const void* p) {
    uint32_t a;
    asm("{ .reg .u64 t; cvta.to.shared.u64 t, %1; cvt.u32.u64 %0, t; }" : "=r"(a) : "l"(p));
    return a;
}

// ---------------- weight pack kernels ----------------
__global__ void transpose_w(const float* __restrict__ src, __half* __restrict__ dst,
                            int K, int N) {
    int i = blockIdx.x * 256 + threadIdx.x;
    if (i < K * N) {
        int n = i / K, k = i % K;
        dst[i] = __float2half_rn(src[(size_t)k * N + n]);
    }
}

__global__ void pack_qkv_t(const float* __restrict__ Wq, const float* __restrict__ Wk,
                           const float* __restrict__ Wv, const float* __restrict__ bq,
                           const float* __restrict__ bk, const float* __restrict__ bv) {
    int i = blockIdx.x * 256 + threadIdx.x;
    if (i < NQKV * CC) {
        int n = i / CC;                  // output feature 0..1151
        int k = i % CC;
        int s2 = n / CC;                 // 0,1,2 selects Q/K/V
        int nn = n % CC;                 // h*HS + d
        const float* src = (s2 == 0) ? Wq : (s2 == 1) ? Wk : Wv;
        g_WqkvT[i] = __float2half_rn(src[(nn / HS) * (CC * HS) + k * HS + (nn % HS)]);
    }
    if (i < NQKV) {
        int s2 = i / CC;
        int nn = i % CC;
        const float* sb = (s2 == 0) ? bq : (s2 == 1) ? bk : bv;
        g_bqkv[i] = sb[nn];
    }
}

// ---------------- LayerNorm (f32 in, half out) ----------------
__global__ __launch_bounds__(128) void ln_kernel(const float* __restrict__ x,
                                                 const float* __restrict__ w,
                                                 const float* __restrict__ b,
                                                 __half* __restrict__ y) {
    int row = blockIdx.x;
    const float* xr = x + (size_t)row * CC;
    int tid = threadIdx.x;
    float v0 = xr[tid], v1 = xr[tid + 128], v2 = xr[tid + 256];
    float s = v0 + v1 + v2;
    float ss = v0 * v0 + v1 * v1 + v2 * v2;
    __shared__ float red[8];
    #pragma unroll
    for (int o = 16; o > 0; o >>= 1) {
        s += __shfl_down_sync(0xffffffffu, s, o);
        ss += __shfl_down_sync(0xffffffffu, ss, o);
    }
    int wid = tid >> 5, lid = tid & 31;
    if (lid == 0) { red[wid] = s; red[4 + wid] = ss; }
    __syncthreads();
    if (tid == 0) {
        float S = red[0] + red[1] + red[2] + red[3];
        float SS = red[4] + red[5] + red[6] + red[7];
        float mean = S * (1.0f / CC);
        float var = SS * (1.0f / CC) - mean * mean;
        red[0] = mean;
        red[1] = rsqrtf(var + 1e-5f);
    }
    __syncthreads();
    float mean = red[0], inv = red[1];
    __half* yr = y + (size_t)row * CC;
    yr[tid]       = __float2half_rn((v0 - mean) * inv * w[tid]       + b[tid]);
    yr[tid + 128] = __float2half_rn((v1 - mean) * inv * w[tid + 128] + b[tid + 128]);
    yr[tid + 256] = __float2half_rn((v2 - mean) * inv * w[tid + 256] + b[tid + 256]);
}

// ---------------- fp16 mma.sync GEMM, cp.async double buffered ----------------
// C[M,N] = A[M,K] @ Bt[N,K]^T + bias ; MODE 0 bias, 1 bias+residual, 2 gelu(bias)
// OUTH: 1 -> write half, 0 -> write float
// CTA tile 128x128, 8 warps (2M x 4N), warp tile 64x32, m16n8k16 fp16, K-chunk 64.
#define PAD_H 72                       // halves per smem row (64 data + 8 pad) = 144B
#define STAGE_B (128 * PAD_H * 2)      // 18432 bytes per matrix per stage
#define SMEM_TOTAL_G (4 * STAGE_B)     // 73728 bytes

__device__ __forceinline__ void mma_f16(float* c, const uint32_t* a, const uint32_t* b) {
    asm volatile(
        "mma.sync.aligned.m16n8k16.row.col.f32.f16.f16.f32 "
        "{%0,%1,%2,%3}, {%4,%5,%6,%7}, {%8,%9}, {%0,%1,%2,%3};"
        : "+f"(c[0]), "+f"(c[1]), "+f"(c[2]), "+f"(c[3])
        : "r"(a[0]), "r"(a[1]), "r"(a[2]), "r"(a[3]), "r"(b[0]), "r"(b[1]));
}

__device__ __forceinline__ void cp16(uint32_t dst, const void* src) {
    asm volatile("cp.async.ca.shared.global [%0], [%1], 16;" :: "r"(dst), "l"(src));
}

template <int MODE, int OUTH>
__global__ __launch_bounds__(256) void mma_gemm16(const __half* __restrict__ A,
                                                  const __half* __restrict__ Bt,
                                                  const float* __restrict__ bias,
                                                  const float* __restrict__ Rres,
                                                  void* __restrict__ Cout,
                                                  int M, int N, int K) {
    extern __shared__ __align__(16) char smem[];
    int tid = threadIdx.x;
    int lane = tid & 31, wid = tid >> 5;
    int warpM = wid & 1, warpN = wid >> 1;
    int g = lane >> 2, tg = lane & 3;
    int row0 = blockIdx.y * 128, col0 = blockIdx.x * 128;

    uint32_t sbase = smem_u32(smem);
    int ldRow = tid >> 1;                 // 0..127
    int ldColH = (tid & 1) * 32;          // half index within chunk row
    const __half* Ap = A + (size_t)(row0 + ldRow) * K + ldColH;
    const __half* Bp = Bt + (size_t)(col0 + ldRow) * K + ldColH;
    uint32_t dOff = (uint32_t)(ldRow * PAD_H + ldColH) * 2;

    int nc = K / 64;

    // stage issue: copies one K=64 chunk of A and B into buffer buf
    auto issue = [&](int c, int buf) {
        uint32_t dA = sbase + (uint32_t)buf * (2 * STAGE_B) + dOff;
        uint32_t dB = dA + STAGE_B;
        const __half* sa = Ap + c * 64;
        const __half* sb = Bp + c * 64;
        #pragma unroll
        for (int j = 0; j < 4; j++) {
            cp16(dA + j * 16, sa + j * 8);
            cp16(dB + j * 16, sb + j * 8);
        }
        asm volatile("cp.async.commit_group;" ::: "memory");
    };

    float acc[4][4][4];
    #pragma unroll
    for (int mi = 0; mi < 4; mi++)
        #pragma unroll
        for (int ni = 0; ni < 4; ni++)
            #pragma unroll
            for (int r = 0; r < 4; r++) acc[mi][ni][r] = 0.0f;

    issue(0, 0);
    if (nc > 1) issue(1, 1);

    for (int c = 0; c < nc; c++) {
        if (c + 1 < nc)
            asm volatile("cp.async.wait_group 1;" ::: "memory");
        else
            asm volatile("cp.async.wait_group 0;" ::: "memory");
        __syncthreads();

        const __half* sAh = (const __half*)(smem + (c & 1) * (2 * STAGE_B));
        const __half* sBh = (const __half*)((const char*)sAh + STAGE_B);

        #pragma unroll
        for (int ks = 0; ks < 4; ks++) {
            int kb = ks * 16;
            uint32_t afr[4][4], bfr[4][2];
            #pragma unroll
            for (int mi = 0; mi < 4; mi++) {
                int m0 = warpM * 64 + mi * 16;
                afr[mi][0] = *(const uint32_t*)&sAh[(m0 + g) * PAD_H + kb + 2 * tg];
                afr[mi][1] = *(const uint32_t*)&sAh[(m0 + g + 8) * PAD_H + kb + 2 * tg];
                afr[mi][2] = *(const uint32_t*)&sAh[(m0 + g) * PAD_H + kb + 8 + 2 * tg];
                afr[mi][3] = *(const uint32_t*)&sAh[(m0 + g + 8) * PAD_H + kb + 8 + 2 * tg];
            }
            #pragma unroll
            for (int ni = 0; ni < 4; ni++) {
                int n0 = warpN * 32 + ni * 8;
                bfr[ni][0] = *(const uint32_t*)&sBh[(n0 + g) * PAD_H + kb + 2 * tg];
                bfr[ni][1] = *(const uint32_t*)&sBh[(n0 + g) * PAD_H + kb + 8 + 2 * tg];
            }
            #pragma unroll
            for (int mi = 0; mi < 4; mi++)
                #pragma unroll
                for (int ni = 0; ni < 4; ni++)
                    mma_f16(acc[mi][ni], afr[mi], bfr[ni]);
        }
        __syncthreads();
        if (c + 2 < nc) issue(c + 2, c & 1);
    }

    // epilogue
    #pragma unroll
    for (int mi = 0; mi < 4; mi++) {
        #pragma unroll
        for (int ni = 0; ni < 4; ni++) {
            int rA = row0 + warpM * 64 + mi * 16 + g;
            int cA = col0 + warpN * 32 + ni * 8 + tg * 2;
            float b0 = bias[cA], b1 = bias[cA + 1];
            #pragma unroll
            for (int half = 0; half < 2; half++) {
                int r = rA + half * 8;
                float o0 = acc[mi][ni][half * 2 + 0] + b0;
                float o1 = acc[mi][ni][half * 2 + 1] + b1;
                size_t idx = (size_t)r * N + cA;
                if (MODE == 1) {
                    const float2 rr = *(const float2*)&Rres[idx];
                    o0 += rr.x; o1 += rr.y;
                }
                if (MODE == 2) {
                    o0 = 0.5f * o0 * (1.0f + erff(o0 * 0.70710678118654752f));
                    o1 = 0.5f * o1 * (1.0f + erff(o1 * 0.70710678118654752f));
                }
                if (OUTH) {
                    *(__half2*)((__half*)Cout + idx) = __floats2half2_rn(o0, o1);
                } else {
                    *(float2*)((float*)Cout + idx) = make_float2(o0, o1);
                }
            }
        }
    }
}

// ---------------- f32x2 helpers for attention ----------------
__device__ __forceinline__ unsigned long long pk2(float lo, float hi) {
    unsigned long long r;
    asm("mov.b64 %0, {%1, %2};" : "=l"(r) : "f"(lo), "f"(hi));
    return r;
}
__device__ __forceinline__ float2 up2(unsigned long long v) {
    float2 r;
    asm("mov.b64 {%0, %1}, %2;" : "=f"(r.x), "=f"(r.y) : "l"(v));
    return r;
}
__device__ __forceinline__ unsigned long long ffma2(unsigned long long a,
                                                    unsigned long long b,
                                                    unsigned long long c) {
    unsigned long long d;
    asm("fma.rn.f32x2 %0, %1, %2, %3;" : "=l"(d) : "l"(a), "l"(b), "l"(c));
    return d;
}
__device__ __forceinline__ unsigned long long fmul2(unsigned long long a,
                                                    unsigned long long b) {
    unsigned long long d;
    asm("mul.rn.f32x2 %0, %1, %2;" : "=l"(d) : "l"(a), "l"(b));
    return d;
}

// ---------------- causal attention: one CTA per (b,h), K/V in smem ----------------
// qkv f32 [M,1152]; output half (head-concat layout)
__global__ __launch_bounds__(256) void attn_kernel(const float* __restrict__ qkv,
                                                   __half* __restrict__ o) {
    extern __shared__ float sm[];
    float* Ks = sm;
    float* Vs = sm + TT * HS;
    int bh = blockIdx.x;
    int b = bh / HH, h = bh % HH;
    size_t base = (size_t)b * TT * NQKV + h * HS;
    int tid = threadIdx.x;

    for (int i = tid; i < TT * HS / 4; i += 256) {
        int s = i >> 4;
        int j = (i & 15) << 2;
        *(float4*)&Ks[s * HS + j] = *(const float4*)&qkv[base + (size_t)s * NQKV + CC + j];
        *(float4*)&Vs[s * HS + j] = *(const float4*)&qkv[base + (size_t)s * NQKV + 2 * CC + j];
    }
    __syncthreads();

    int t = tid;
    unsigned long long q2[32];
    #pragma unroll
    for (int j = 0; j < 16; j++) {
        ulonglong2 v = *(const ulonglong2*)&qkv[base + (size_t)t * NQKV + 4 * j];
        q2[2 * j] = v.x;
        q2[2 * j + 1] = v.y;
    }
    unsigned long long acc2[32];
    #pragma unroll
    for (int j = 0; j < 32; j++) acc2[j] = 0ull;

    float m = -1e30f, l = 0.0f;
    for (int s = 0; s <= t; s++) {
        const ulonglong2* kp = (const ulonglong2*)&Ks[s * HS];
        unsigned long long d2 = 0ull;
        #pragma unroll
        for (int j = 0; j < 16; j++) {
            ulonglong2 kk = kp[j];
            d2 = ffma2(q2[2 * j], kk.x, d2);
            d2 = ffma2(q2[2 * j + 1], kk.y, d2);
        }
        float2 df = up2(d2);
        float dot = (df.x + df.y) * 0.125f;
        float mn = fmaxf(m, dot);
        float a = __expf(m - mn);
        float p = __expf(dot - mn);
        l = l * a + p;
        unsigned long long a2 = pk2(a, a);
        unsigned long long p2 = pk2(p, p);
        const ulonglong2* vp = (const ulonglong2*)&Vs[s * HS];
        #pragma unroll
        for (int j = 0; j < 16; j++) {
            ulonglong2 vv = vp[j];
            acc2[2 * j]     = ffma2(acc2[2 * j],     a2, fmul2(p2, vv.x));
            acc2[2 * j + 1] = ffma2(acc2[2 * j + 1], a2, fmul2(p2, vv.y));
        }
        m = mn;
    }
    float invl = 1.0f / l;
    __half* op = o + (size_t)(b * TT + t) * CC + h * HS;
    #pragma unroll
    for (int j = 0; j < 16; j++) {
        float2 v0 = up2(acc2[2 * j]);
        float2 v1 = up2(acc2[2 * j + 1]);
        *(__half2*)&op[4 * j]     = __floats2half2_rn(v0.x * invl, v0.y * invl);
        *(__half2*)&op[4 * j + 2] = __floats2half2_rn(v1.x * invl, v1.y * invl);
    }
}

// ---------------- launch ----------------
extern "C" void kernel_launch(void* const* d_in, const int* in_sizes, int n_in,
                              void* d_out, int out_size) {
    const float* x     = (const float*)d_in[0];
    const float* ln1w  = (const float*)d_in[1];
    const float* ln1b  = (const float*)d_in[2];
    const float* Wq    = (const float*)d_in[3];
    const float* bq    = (const float*)d_in[4];
    const float* Wk    = (const float*)d_in[5];
    const float* bk    = (const float*)d_in[6];
    const float* Wv    = (const float*)d_in[7];
    const float* bv    = (const float*)d_in[8];
    const float* Wproj = (const float*)d_in[9];
    const float* bproj = (const float*)d_in[10];
    const float* ln2w  = (const float*)d_in[11];
    const float* ln2b  = (const float*)d_in[12];
    const float* W1    = (const float*)d_in[13];
    const float* b1    = (const float*)d_in[14];
    const float* W2    = (const float*)d_in[15];
    const float* b2    = (const float*)d_in[16];
    float* out = (float*)d_out;

    __half *h, *o, *f1, *wqkvT, *wprojT, *w1T, *w2T;
    float *qkv, *x1, *bqkv;
    cudaGetSymbolAddress((void**)&h, g_h);
    cudaGetSymbolAddress((void**)&qkv, g_qkv);
    cudaGetSymbolAddress((void**)&o, g_o);
    cudaGetSymbolAddress((void**)&x1, g_x1);
    cudaGetSymbolAddress((void**)&f1, g_f1);
    cudaGetSymbolAddress((void**)&wqkvT, g_WqkvT);
    cudaGetSymbolAddress((void**)&wprojT, g_WprojT);
    cudaGetSymbolAddress((void**)&w1T, g_W1T);
    cudaGetSymbolAddress((void**)&w2T, g_W2T);
    cudaGetSymbolAddress((void**)&bqkv, g_bqkv);

    cudaFuncSetAttribute(attn_kernel, cudaFuncAttributeMaxDynamicSharedMemorySize,
                         2 * TT * HS * (int)sizeof(float));
    cudaFuncSetAttribute(mma_gemm16<0, 0>, cudaFuncAttributeMaxDynamicSharedMemorySize, SMEM_TOTAL_G);
    cudaFuncSetAttribute(mma_gemm16<1, 0>, cudaFuncAttributeMaxDynamicSharedMemorySize, SMEM_TOTAL_G);
    cudaFuncSetAttribute(mma_gemm16<2, 1>, cudaFuncAttributeMaxDynamicSharedMemorySize, SMEM_TOTAL_G);

    // weight packing (fp16, transposed to [N,K])
    pack_qkv_t<<<(NQKV * CC + 255) / 256, 256>>>(Wq, Wk, Wv, bq, bk, bv);
    transpose_w<<<(CC * CC + 255) / 256, 256>>>(Wproj, wprojT, CC, CC);
    transpose_w<<<(CF * CC + 255) / 256, 256>>>(W1, w1T, CC, CF);
    transpose_w<<<(CC * CF + 255) / 256, 256>>>(W2, w2T, CF, CC);

    // LN1 (-> half)
    ln_kernel<<<MM, 128>>>(x, ln1w, ln1b, h);
    // QKV GEMM (half x half -> f32)
    mma_gemm16<0, 0><<<dim3(NQKV / 128, MM / 128), 256, SMEM_TOTAL_G>>>(h, wqkvT, bqkv, nullptr, qkv, MM, NQKV, CC);
    // attention (f32 in, half out)
    attn_kernel<<<BB * HH, 256, 2 * TT * HS * (int)sizeof(float)>>>(qkv, o);
    // proj + residual (-> f32 x1)
    mma_gemm16<1, 0><<<dim3(CC / 128, MM / 128), 256, SMEM_TOTAL_G>>>(o, wprojT, bproj, x, x1, MM, CC, CC);
    // LN2 (-> half)
    ln_kernel<<<MM, 128>>>(x1, ln2w, ln2b, h);
    // FFN1 + GELU (-> half f1)
    mma_gemm16<2, 1><<<dim3(CF / 128, MM / 128), 256, SMEM_TOTAL_G>>>(h, w1T, b1, nullptr, f1, MM, CF, CC);
    // FFN2 + residual (-> f32 out)
    mma_gemm16<1, 0><<<dim3(CC / 128, MM / 128), 256, SMEM_TOTAL_G>>>(f1, w2T, b2, x1, out, MM, CC, CF);
}

// round 6
// speedup vs baseline: 4.8215x; 1.4612x over previous
#include <cuda_runtime.h>
#include <cuda_fp16.h>
#include <math.h>
#include <cstdint>

// Problem constants
#define BB 64
#define TT 256
#define CC 384
#define HH 6
#define HS 64
#define MM (BB * TT)          // 16384
#define NQKV (3 * CC)         // 1152
#define CF (4 * CC)           // 1536

// ---------------- scratch (static __device__, no allocs) ----------------
__device__ __half g_h[MM * CC];       // ln output (half, GEMM A input)
__device__ __half g_qkvh[MM * NQKV];  // packed Q|K|V (half)
__device__ __half g_o[MM * CC];       // attention output (half)
__device__ float  g_x1[MM * CC];      // first residual (f32)
__device__ __half g_f1[MM * CF];      // FFN hidden (half)
// transposed (N-major, K-contig) fp16 weights
__device__ __half g_WqkvT[NQKV * CC];
__device__ __half g_WprojT[CC * CC];
__device__ __half g_W1T[CF * CC];
__device__ __half g_W2T[CC * CF];
__device__ float  g_bqkv[NQKV];

__device__ __forceinline__ uint32_t smem_u32(const void* p) {
    uint32_t a;
    asm("{ .reg .u64 t; cvta.to.shared.u64 t, %1; cvt.u32.u64 %0, t; }" : "=r"(a) : "l"(p));
    return a;
}

// ---------------- weight pack kernels ----------------
__global__ void transpose_w(const float* __restrict__ src, __half* __restrict__ dst,
                            int K, int N) {
    int i = blockIdx.x * 256 + threadIdx.x;
    if (i < K * N) {
        int n = i / K, k = i % K;
        dst[i] = __float2half_rn(src[(size_t)k * N + n]);
    }
}

__global__ void pack_qkv_t(const float* __restrict__ Wq, const float* __restrict__ Wk,
                           const float* __restrict__ Wv, const float* __restrict__ bq,
                           const float* __restrict__ bk, const float* __restrict__ bv) {
    int i = blockIdx.x * 256 + threadIdx.x;
    if (i < NQKV * CC) {
        int n = i / CC;                  // output feature 0..1151
        int k = i % CC;
        int s2 = n / CC;                 // 0,1,2 selects Q/K/V
        int nn = n % CC;                 // h*HS + d
        const float* src = (s2 == 0) ? Wq : (s2 == 1) ? Wk : Wv;
        g_WqkvT[i] = __float2half_rn(src[(nn / HS) * (CC * HS) + k * HS + (nn % HS)]);
    }
    if (i < NQKV) {
        int s2 = i / CC;
        int nn = i % CC;
        const float* sb = (s2 == 0) ? bq : (s2 == 1) ? bk : bv;
        g_bqkv[i] = sb[nn];
    }
}

// ---------------- LayerNorm (f32 in, half out) ----------------
__global__ __launch_bounds__(128) void ln_kernel(const float* __restrict__ x,
                                                 const float* __restrict__ w,
                                                 const float* __restrict__ b,
                                                 __half* __restrict__ y) {
    int row = blockIdx.x;
    const float* xr = x + (size_t)row * CC;
    int tid = threadIdx.x;
    float v0 = xr[tid], v1 = xr[tid + 128], v2 = xr[tid + 256];
    float s = v0 + v1 + v2;
    float ss = v0 * v0 + v1 * v1 + v2 * v2;
    __shared__ float red[8];
    #pragma unroll
    for (int o = 16; o > 0; o >>= 1) {
        s += __shfl_down_sync(0xffffffffu, s, o);
        ss += __shfl_down_sync(0xffffffffu, ss, o);
    }
    int wid = tid >> 5, lid = tid & 31;
    if (lid == 0) { red[wid] = s; red[4 + wid] = ss; }
    __syncthreads();
    if (tid == 0) {
        float S = red[0] + red[1] + red[2] + red[3];
        float SS = red[4] + red[5] + red[6] + red[7];
        float mean = S * (1.0f / CC);
        float var = SS * (1.0f / CC) - mean * mean;
        red[0] = mean;
        red[1] = rsqrtf(var + 1e-5f);
    }
    __syncthreads();
    float mean = red[0], inv = red[1];
    __half* yr = y + (size_t)row * CC;
    yr[tid]       = __float2half_rn((v0 - mean) * inv * w[tid]       + b[tid]);
    yr[tid + 128] = __float2half_rn((v1 - mean) * inv * w[tid + 128] + b[tid + 128]);
    yr[tid + 256] = __float2half_rn((v2 - mean) * inv * w[tid + 256] + b[tid + 256]);
}

// ---------------- fp16 mma helpers ----------------
__device__ __forceinline__ void mma_f16(float* c, const uint32_t* a, const uint32_t* b) {
    asm volatile(
        "mma.sync.aligned.m16n8k16.row.col.f32.f16.f16.f32 "
        "{%0,%1,%2,%3}, {%4,%5,%6,%7}, {%8,%9}, {%0,%1,%2,%3};"
        : "+f"(c[0]), "+f"(c[1]), "+f"(c[2]), "+f"(c[3])
        : "r"(a[0]), "r"(a[1]), "r"(a[2]), "r"(a[3]), "r"(b[0]), "r"(b[1]));
}

__device__ __forceinline__ void cp16(uint32_t dst, const void* src) {
    asm volatile("cp.async.ca.shared.global [%0], [%1], 16;" :: "r"(dst), "l"(src));
}
__device__ __forceinline__ uint32_t h2u(__half2 v) {
    return *(uint32_t*)&v;
}

// ---------------- fp16 mma.sync GEMM, cp.async double buffered ----------------
#define PAD_H 72
#define STAGE_B (128 * PAD_H * 2)
#define SMEM_TOTAL_G (4 * STAGE_B)

template <int MODE, int OUTH>
__global__ __launch_bounds__(256) void mma_gemm16(const __half* __restrict__ A,
                                                  const __half* __restrict__ Bt,
                                                  const float* __restrict__ bias,
                                                  const float* __restrict__ Rres,
                                                  void* __restrict__ Cout,
                                                  int M, int N, int K) {
    extern __shared__ __align__(16) char smem[];
    int tid = threadIdx.x;
    int lane = tid & 31, wid = tid >> 5;
    int warpM = wid & 1, warpN = wid >> 1;
    int g = lane >> 2, tg = lane & 3;
    int row0 = blockIdx.y * 128, col0 = blockIdx.x * 128;

    uint32_t sbase = smem_u32(smem);
    int ldRow = tid >> 1;
    int ldColH = (tid & 1) * 32;
    const __half* Ap = A + (size_t)(row0 + ldRow) * K + ldColH;
    const __half* Bp = Bt + (size_t)(col0 + ldRow) * K + ldColH;
    uint32_t dOff = (uint32_t)(ldRow * PAD_H + ldColH) * 2;

    int nc = K / 64;

    auto issue = [&](int c, int buf) {
        uint32_t dA = sbase + (uint32_t)buf * (2 * STAGE_B) + dOff;
        uint32_t dB = dA + STAGE_B;
        const __half* sa = Ap + c * 64;
        const __half* sb = Bp + c * 64;
        #pragma unroll
        for (int j = 0; j < 4; j++) {
            cp16(dA + j * 16, sa + j * 8);
            cp16(dB + j * 16, sb + j * 8);
        }
        asm volatile("cp.async.commit_group;" ::: "memory");
    };

    float acc[4][4][4];
    #pragma unroll
    for (int mi = 0; mi < 4; mi++)
        #pragma unroll
        for (int ni = 0; ni < 4; ni++)
            #pragma unroll
            for (int r = 0; r < 4; r++) acc[mi][ni][r] = 0.0f;

    issue(0, 0);
    if (nc > 1) issue(1, 1);

    for (int c = 0; c < nc; c++) {
        if (c + 1 < nc)
            asm volatile("cp.async.wait_group 1;" ::: "memory");
        else
            asm volatile("cp.async.wait_group 0;" ::: "memory");
        __syncthreads();

        const __half* sAh = (const __half*)(smem + (c & 1) * (2 * STAGE_B));
        const __half* sBh = (const __half*)((const char*)sAh + STAGE_B);

        #pragma unroll
        for (int ks = 0; ks < 4; ks++) {
            int kb = ks * 16;
            uint32_t afr[4][4], bfr[4][2];
            #pragma unroll
            for (int mi = 0; mi < 4; mi++) {
                int m0 = warpM * 64 + mi * 16;
                afr[mi][0] = *(const uint32_t*)&sAh[(m0 + g) * PAD_H + kb + 2 * tg];
                afr[mi][1] = *(const uint32_t*)&sAh[(m0 + g + 8) * PAD_H + kb + 2 * tg];
                afr[mi][2] = *(const uint32_t*)&sAh[(m0 + g) * PAD_H + kb + 8 + 2 * tg];
                afr[mi][3] = *(const uint32_t*)&sAh[(m0 + g + 8) * PAD_H + kb + 8 + 2 * tg];
            }
            #pragma unroll
            for (int ni = 0; ni < 4; ni++) {
                int n0 = warpN * 32 + ni * 8;
                bfr[ni][0] = *(const uint32_t*)&sBh[(n0 + g) * PAD_H + kb + 2 * tg];
                bfr[ni][1] = *(const uint32_t*)&sBh[(n0 + g) * PAD_H + kb + 8 + 2 * tg];
            }
            #pragma unroll
            for (int mi = 0; mi < 4; mi++)
                #pragma unroll
                for (int ni = 0; ni < 4; ni++)
                    mma_f16(acc[mi][ni], afr[mi], bfr[ni]);
        }
        __syncthreads();
        if (c + 2 < nc) issue(c + 2, c & 1);
    }

    #pragma unroll
    for (int mi = 0; mi < 4; mi++) {
        #pragma unroll
        for (int ni = 0; ni < 4; ni++) {
            int rA = row0 + warpM * 64 + mi * 16 + g;
            int cA = col0 + warpN * 32 + ni * 8 + tg * 2;
            float b0 = bias[cA], b1 = bias[cA + 1];
            #pragma unroll
            for (int half = 0; half < 2; half++) {
                int r = rA + half * 8;
                float o0 = acc[mi][ni][half * 2 + 0] + b0;
                float o1 = acc[mi][ni][half * 2 + 1] + b1;
                size_t idx = (size_t)r * N + cA;
                if (MODE == 1) {
                    const float2 rr = *(const float2*)&Rres[idx];
                    o0 += rr.x; o1 += rr.y;
                }
                if (MODE == 2) {
                    o0 = 0.5f * o0 * (1.0f + erff(o0 * 0.70710678118654752f));
                    o1 = 0.5f * o1 * (1.0f + erff(o1 * 0.70710678118654752f));
                }
                if (OUTH) {
                    *(__half2*)((__half*)Cout + idx) = __floats2half2_rn(o0, o1);
                } else {
                    *(float2*)((float*)Cout + idx) = make_float2(o0, o1);
                }
            }
        }
    }
}

// ---------------- flash attention with fp16 mma ----------------
// grid: ((b*HH + h)*2 + qt), 8 warps, warp = 16 q rows; key tiles of 64.
#define KS_STR 72
#define VT_STR 264
#define ATT_SMEM ((256 * KS_STR + HS * VT_STR) * 2)   // 70656 bytes

__global__ __launch_bounds__(256) void attn_mma(const __half* __restrict__ qkv,
                                                __half* __restrict__ o) {
    extern __shared__ __align__(16) __half smh[];
    __half* Ks = smh;                      // [256][KS_STR]
    __half* Vt = smh + 256 * KS_STR;       // [64][VT_STR]
    int idx = blockIdx.x;
    int qt = idx & 1;
    int h = (idx >> 1) % HH;
    int b = idx / (2 * HH);
    size_t base = (size_t)b * TT * NQKV + (size_t)h * HS;
    int tid = threadIdx.x;
    int wid = tid >> 5, lane = tid & 31;
    int g = lane >> 2, tg = lane & 3;

    int nkeys = qt ? 256 : 128;
    // K tile: [nkeys][64]
    for (int i = tid; i < nkeys * 8; i += 256) {
        int row = i >> 3, seg = i & 7;
        *(float4*)&Ks[row * KS_STR + seg * 8] =
            *(const float4*)&qkv[base + CC + (size_t)row * NQKV + seg * 8];
    }
    // V transposed: warp wid handles keys wid, wid+8, ...; lane covers d pair
    for (int k = wid; k < nkeys; k += 8) {
        __half2 v2 = *(const __half2*)&qkv[base + 2 * CC + (size_t)k * NQKV + 2 * lane];
        Vt[(2 * lane) * VT_STR + k] = __low2half(v2);
        Vt[(2 * lane + 1) * VT_STR + k] = __high2half(v2);
    }
    __syncthreads();

    int qbase = qt * 128 + wid * 16;     // sequence-local base row of this warp
    // Q fragments: [ks][4]
    uint32_t qf[4][4];
    const __half* qp = &qkv[base + (size_t)(b ? 0 : 0) + (size_t)(qt * 128 + wid * 16) * NQKV];
    #pragma unroll
    for (int ks = 0; ks < 4; ks++) {
        int d0 = ks * 16;
        qf[ks][0] = *(const uint32_t*)&qp[(size_t)g * NQKV + d0 + 2 * tg];
        qf[ks][1] = *(const uint32_t*)&qp[(size_t)(g + 8) * NQKV + d0 + 2 * tg];
        qf[ks][2] = *(const uint32_t*)&qp[(size_t)g * NQKV + d0 + 8 + 2 * tg];
        qf[ks][3] = *(const uint32_t*)&qp[(size_t)(g + 8) * NQKV + d0 + 8 + 2 * tg];
    }

    float Oa[8][4];
    #pragma unroll
    for (int nb = 0; nb < 8; nb++)
        #pragma unroll
        for (int j = 0; j < 4; j++) Oa[nb][j] = 0.0f;
    float m0 = -1e30f, m1 = -1e30f, l0 = 0.0f, l1 = 0.0f;

    int ktmax = (qbase + 15) >> 6;
    for (int kt = 0; kt <= ktmax; kt++) {
        float S[8][4];
        #pragma unroll
        for (int nb = 0; nb < 8; nb++)
            #pragma unroll
            for (int j = 0; j < 4; j++) S[nb][j] = 0.0f;

        // S = Q @ K^T for this 64-key tile
        #pragma unroll
        for (int nb = 0; nb < 8; nb++) {
            int krow = (kt * 64 + nb * 8 + g) * KS_STR;
            #pragma unroll
            for (int ks = 0; ks < 4; ks++) {
                uint32_t bf[2];
                bf[0] = *(const uint32_t*)&Ks[krow + ks * 16 + 2 * tg];
                bf[1] = *(const uint32_t*)&Ks[krow + ks * 16 + 8 + 2 * tg];
                mma_f16(S[nb], qf[ks], bf);
            }
        }
        // scale
        #pragma unroll
        for (int nb = 0; nb < 8; nb++)
            #pragma unroll
            for (int j = 0; j < 4; j++) S[nb][j] *= 0.125f;
        // causal mask (only the diagonal tile)
        if (kt == ktmax) {
            int r0 = qbase + g, r1 = r0 + 8;
            #pragma unroll
            for (int nb = 0; nb < 8; nb++) {
                int col = kt * 64 + nb * 8 + 2 * tg;
                if (col > r0)     S[nb][0] = -1e30f;
                if (col + 1 > r0) S[nb][1] = -1e30f;
                if (col > r1)     S[nb][2] = -1e30f;
                if (col + 1 > r1) S[nb][3] = -1e30f;
            }
        }
        // row max
        float tm0 = -1e30f, tm1 = -1e30f;
        #pragma unroll
        for (int nb = 0; nb < 8; nb++) {
            tm0 = fmaxf(tm0, fmaxf(S[nb][0], S[nb][1]));
            tm1 = fmaxf(tm1, fmaxf(S[nb][2], S[nb][3]));
        }
        tm0 = fmaxf(tm0, __shfl_xor_sync(0xffffffffu, tm0, 1));
        tm0 = fmaxf(tm0, __shfl_xor_sync(0xffffffffu, tm0, 2));
        tm1 = fmaxf(tm1, __shfl_xor_sync(0xffffffffu, tm1, 1));
        tm1 = fmaxf(tm1, __shfl_xor_sync(0xffffffffu, tm1, 2));
        float mn0 = fmaxf(m0, tm0), mn1 = fmaxf(m1, tm1);
        float sc0 = __expf(m0 - mn0), sc1 = __expf(m1 - mn1);
        // exponentiate + row sums
        float ts0 = 0.0f, ts1 = 0.0f;
        #pragma unroll
        for (int nb = 0; nb < 8; nb++) {
            S[nb][0] = __expf(S[nb][0] - mn0);
            S[nb][1] = __expf(S[nb][1] - mn0);
            S[nb][2] = __expf(S[nb][2] - mn1);
            S[nb][3] = __expf(S[nb][3] - mn1);
            ts0 += S[nb][0] + S[nb][1];
            ts1 += S[nb][2] + S[nb][3];
        }
        ts0 += __shfl_xor_sync(0xffffffffu, ts0, 1);
        ts0 += __shfl_xor_sync(0xffffffffu, ts0, 2);
        ts1 += __shfl_xor_sync(0xffffffffu, ts1, 1);
        ts1 += __shfl_xor_sync(0xffffffffu, ts1, 2);
        l0 = l0 * sc0 + ts0;
        l1 = l1 * sc1 + ts1;
        m0 = mn0; m1 = mn1;
        // rescale O
        #pragma unroll
        for (int nb = 0; nb < 8; nb++) {
            Oa[nb][0] *= sc0; Oa[nb][1] *= sc0;
            Oa[nb][2] *= sc1; Oa[nb][3] *= sc1;
        }
        // O += P @ V
        #pragma unroll
        for (int ks = 0; ks < 4; ks++) {
            uint32_t ap[4];
            ap[0] = h2u(__floats2half2_rn(S[2 * ks][0], S[2 * ks][1]));
            ap[1] = h2u(__floats2half2_rn(S[2 * ks][2], S[2 * ks][3]));
            ap[2] = h2u(__floats2half2_rn(S[2 * ks + 1][0], S[2 * ks + 1][1]));
            ap[3] = h2u(__floats2half2_rn(S[2 * ks + 1][2], S[2 * ks + 1][3]));
            int k0 = kt * 64 + ks * 16;
            #pragma unroll
            for (int nb = 0; nb < 8; nb++) {
                uint32_t bf[2];
                bf[0] = *(const uint32_t*)&Vt[(nb * 8 + g) * VT_STR + k0 + 2 * tg];
                bf[1] = *(const uint32_t*)&Vt[(nb * 8 + g) * VT_STR + k0 + 8 + 2 * tg];
                mma_f16(Oa[nb], ap, bf);
            }
        }
    }

    float inv0 = 1.0f / l0, inv1 = 1.0f / l1;
    __half* op = o + ((size_t)(b * TT + qt * 128 + wid * 16 + g) * CC + h * HS);
    __half* op1 = op + 8 * CC;
    #pragma unroll
    for (int nb = 0; nb < 8; nb++) {
        *(__half2*)&op[nb * 8 + 2 * tg]  = __floats2half2_rn(Oa[nb][0] * inv0, Oa[nb][1] * inv0);
        *(__half2*)&op1[nb * 8 + 2 * tg] = __floats2half2_rn(Oa[nb][2] * inv1, Oa[nb][3] * inv1);
    }
}

// ---------------- launch ----------------
extern "C" void kernel_launch(void* const* d_in, const int* in_sizes, int n_in,
                              void* d_out, int out_size) {
    const float* x     = (const float*)d_in[0];
    const float* ln1w  = (const float*)d_in[1];
    const float* ln1b  = (const float*)d_in[2];
    const float* Wq    = (const float*)d_in[3];
    const float* bq    = (const float*)d_in[4];
    const float* Wk    = (const float*)d_in[5];
    const float* bk    = (const float*)d_in[6];
    const float* Wv    = (const float*)d_in[7];
    const float* bv    = (const float*)d_in[8];
    const float* Wproj = (const float*)d_in[9];
    const float* bproj = (const float*)d_in[10];
    const float* ln2w  = (const float*)d_in[11];
    const float* ln2b  = (const float*)d_in[12];
    const float* W1    = (const float*)d_in[13];
    const float* b1    = (const float*)d_in[14];
    const float* W2    = (const float*)d_in[15];
    const float* b2    = (const float*)d_in[16];
    float* out = (float*)d_out;

    __half *h, *qkvh, *o, *f1, *wqkvT, *wprojT, *w1T, *w2T;
    float *x1, *bqkv;
    cudaGetSymbolAddress((void**)&h, g_h);
    cudaGetSymbolAddress((void**)&qkvh, g_qkvh);
    cudaGetSymbolAddress((void**)&o, g_o);
    cudaGetSymbolAddress((void**)&x1, g_x1);
    cudaGetSymbolAddress((void**)&f1, g_f1);
    cudaGetSymbolAddress((void**)&wqkvT, g_WqkvT);
    cudaGetSymbolAddress((void**)&wprojT, g_WprojT);
    cudaGetSymbolAddress((void**)&w1T, g_W1T);
    cudaGetSymbolAddress((void**)&w2T, g_W2T);
    cudaGetSymbolAddress((void**)&bqkv, g_bqkv);

    cudaFuncSetAttribute(attn_mma, cudaFuncAttributeMaxDynamicSharedMemorySize, ATT_SMEM);
    cudaFuncSetAttribute(mma_gemm16<0, 1>, cudaFuncAttributeMaxDynamicSharedMemorySize, SMEM_TOTAL_G);
    cudaFuncSetAttribute(mma_gemm16<1, 0>, cudaFuncAttributeMaxDynamicSharedMemorySize, SMEM_TOTAL_G);
    cudaFuncSetAttribute(mma_gemm16<2, 1>, cudaFuncAttributeMaxDynamicSharedMemorySize, SMEM_TOTAL_G);

    // weight packing (fp16, transposed to [N,K])
    pack_qkv_t<<<(NQKV * CC + 255) / 256, 256>>>(Wq, Wk, Wv, bq, bk, bv);
    transpose_w<<<(CC * CC + 255) / 256, 256>>>(Wproj, wprojT, CC, CC);
    transpose_w<<<(CF * CC + 255) / 256, 256>>>(W1, w1T, CC, CF);
    transpose_w<<<(CC * CF + 255) / 256, 256>>>(W2, w2T, CF, CC);

    // LN1 (-> half)
    ln_kernel<<<MM, 128>>>(x, ln1w, ln1b, h);
    // QKV GEMM (half out)
    mma_gemm16<0, 1><<<dim3(NQKV / 128, MM / 128), 256, SMEM_TOTAL_G>>>(h, wqkvT, bqkv, nullptr, qkvh, MM, NQKV, CC);
    // flash attention (half in/out)
    attn_mma<<<BB * HH * 2, 256, ATT_SMEM>>>(qkvh, o);
    // proj + residual (-> f32 x1)
    mma_gemm16<1, 0><<<dim3(CC / 128, MM / 128), 256, SMEM_TOTAL_G>>>(o, wprojT, bproj, x, x1, MM, CC, CC);
    // LN2 (-> half)
    ln_kernel<<<MM, 128>>>(x1, ln2w, ln2b, h);
    // FFN1 + GELU (-> half f1)
    mma_gemm16<2, 1><<<dim3(CF / 128, MM / 128), 256, SMEM_TOTAL_G>>>(h, w1T, b1, nullptr, f1, MM, CF, CC);
    // FFN2 + residual (-> f32 out)
    mma_gemm16<1, 0><<<dim3(CC / 128, MM / 128), 256, SMEM_TOTAL_G>>>(f1, w2T, b2, x1, out, MM, CC, CF);
}

// round 7
// speedup vs baseline: 6.1649x; 1.2786x over previous
#include <cuda_runtime.h>
#include <cuda_fp16.h>
#include <math.h>
#include <cstdint>

// Problem constants
#define BB 64
#define TT 256
#define CC 384
#define HH 6
#define HS 64
#define MM (BB * TT)          // 16384
#define NQKV (3 * CC)         // 1152
#define CF (4 * CC)           // 1536

// ---------------- scratch (static __device__, no allocs) ----------------
__device__ __half g_h[MM * CC];       // ln output (half, GEMM A input)
__device__ __half g_qkvh[MM * NQKV];  // packed Q|K|V (half)
__device__ __half g_o[MM * CC];       // attention output (half)
__device__ float  g_x1[MM * CC];      // first residual (f32)
__device__ __half g_f1[MM * CF];      // FFN hidden (half)
// transposed (N-major, K-contig) fp16 weights
__device__ __half g_WqkvT[NQKV * CC];
__device__ __half g_WprojT[CC * CC];
__device__ __half g_W1T[CF * CC];
__device__ __half g_W2T[CC * CF];
__device__ float  g_bqkv[NQKV];

__device__ __forceinline__ uint32_t smem_u32(const void* p) {
    uint32_t a;
    asm("{ .reg .u64 t; cvta.to.shared.u64 t, %1; cvt.u32.u64 %0, t; }" : "=r"(a) : "l"(p));
    return a;
}

// ---------------- weight pack kernels ----------------
__global__ void transpose_w(const float* __restrict__ src, __half* __restrict__ dst,
                            int K, int N) {
    int i = blockIdx.x * 256 + threadIdx.x;
    if (i < K * N) {
        int n = i / K, k = i % K;
        dst[i] = __float2half_rn(src[(size_t)k * N + n]);
    }
}

__global__ void pack_qkv_t(const float* __restrict__ Wq, const float* __restrict__ Wk,
                           const float* __restrict__ Wv, const float* __restrict__ bq,
                           const float* __restrict__ bk, const float* __restrict__ bv) {
    int i = blockIdx.x * 256 + threadIdx.x;
    if (i < NQKV * CC) {
        int n = i / CC;                  // output feature 0..1151
        int k = i % CC;
        int s2 = n / CC;                 // 0,1,2 selects Q/K/V
        int nn = n % CC;                 // h*HS + d
        const float* src = (s2 == 0) ? Wq : (s2 == 1) ? Wk : Wv;
        g_WqkvT[i] = __float2half_rn(src[(nn / HS) * (CC * HS) + k * HS + (nn % HS)]);
    }
    if (i < NQKV) {
        int s2 = i / CC;
        int nn = i % CC;
        const float* sb = (s2 == 0) ? bq : (s2 == 1) ? bk : bv;
        g_bqkv[i] = sb[nn];
    }
}

// ---------------- LayerNorm (f32 in, half out) ----------------
__global__ __launch_bounds__(128) void ln_kernel(const float* __restrict__ x,
                                                 const float* __restrict__ w,
                                                 const float* __restrict__ b,
                                                 __half* __restrict__ y) {
    int row = blockIdx.x;
    const float* xr = x + (size_t)row * CC;
    int tid = threadIdx.x;
    float v0 = xr[tid], v1 = xr[tid + 128], v2 = xr[tid + 256];
    float s = v0 + v1 + v2;
    float ss = v0 * v0 + v1 * v1 + v2 * v2;
    __shared__ float red[8];
    #pragma unroll
    for (int o = 16; o > 0; o >>= 1) {
        s += __shfl_down_sync(0xffffffffu, s, o);
        ss += __shfl_down_sync(0xffffffffu, ss, o);
    }
    int wid = tid >> 5, lid = tid & 31;
    if (lid == 0) { red[wid] = s; red[4 + wid] = ss; }
    __syncthreads();
    if (tid == 0) {
        float S = red[0] + red[1] + red[2] + red[3];
        float SS = red[4] + red[5] + red[6] + red[7];
        float mean = S * (1.0f / CC);
        float var = SS * (1.0f / CC) - mean * mean;
        red[0] = mean;
        red[1] = rsqrtf(var + 1e-5f);
    }
    __syncthreads();
    float mean = red[0], inv = red[1];
    __half* yr = y + (size_t)row * CC;
    yr[tid]       = __float2half_rn((v0 - mean) * inv * w[tid]       + b[tid]);
    yr[tid + 128] = __float2half_rn((v1 - mean) * inv * w[tid + 128] + b[tid + 128]);
    yr[tid + 256] = __float2half_rn((v2 - mean) * inv * w[tid + 256] + b[tid + 256]);
}

// ---------------- fp16 mma helpers ----------------
__device__ __forceinline__ void mma_f16(float* c, const uint32_t* a, const uint32_t* b) {
    asm volatile(
        "mma.sync.aligned.m16n8k16.row.col.f32.f16.f16.f32 "
        "{%0,%1,%2,%3}, {%4,%5,%6,%7}, {%8,%9}, {%0,%1,%2,%3};"
        : "+f"(c[0]), "+f"(c[1]), "+f"(c[2]), "+f"(c[3])
        : "r"(a[0]), "r"(a[1]), "r"(a[2]), "r"(a[3]), "r"(b[0]), "r"(b[1]));
}

__device__ __forceinline__ void cp16(uint32_t dst, const void* src) {
    asm volatile("cp.async.ca.shared.global [%0], [%1], 16;" :: "r"(dst), "l"(src));
}
__device__ __forceinline__ uint32_t h2u(__half2 v) {
    return *(uint32_t*)&v;
}
__device__ __forceinline__ void ldsm4(uint32_t* r, uint32_t addr) {
    asm volatile("ldmatrix.sync.aligned.m8n8.x4.shared.b16 {%0,%1,%2,%3}, [%4];"
        : "=r"(r[0]), "=r"(r[1]), "=r"(r[2]), "=r"(r[3]) : "r"(addr));
}

// ---------------- fp16 mma.sync GEMM: ldmatrix + XOR swizzle, 2 CTA/SM ----------------
// C[M,N] = A[M,K] @ Bt[N,K]^T + bias ; MODE 0 bias, 1 bias+residual, 2 gelu(bias)
// CTA tile 128x128, 8 warps (2M x 4N), warp 64x32, K-chunk 64 halves (128B rows).
// Smem: row = 128B = 8 x 16B groups; group swizzled by XOR(row&7). No padding.
#define STG_A 16384                    // 128 rows * 128B
#define STG_T 32768                    // A + B per stage
#define SMEM_TOTAL_G 65536             // 2 stages

template <int MODE, int OUTH>
__global__ __launch_bounds__(256, 2) void mma_gemm16(const __half* __restrict__ A,
                                                     const __half* __restrict__ Bt,
                                                     const float* __restrict__ bias,
                                                     const float* __restrict__ Rres,
                                                     void* __restrict__ Cout,
                                                     int M, int N, int K) {
    extern __shared__ __align__(16) char smem[];
    int tid = threadIdx.x;
    int lane = tid & 31, wid = tid >> 5;
    int warpM = wid & 1, warpN = wid >> 1;
    int g = lane >> 2, tg = lane & 3;
    int row0 = blockIdx.y * 128, col0 = blockIdx.x * 128;

    uint32_t sbase = smem_u32(smem);

    // cp.async mapping: 8 threads per row, 16B per thread, 4 passes (32 rows each)
    int cRow = tid >> 3;               // 0..31
    int cGrp = tid & 7;                // 16B group
    const __half* Ag = A + (size_t)(row0 + cRow) * K + cGrp * 8;
    const __half* Bg = Bt + (size_t)(col0 + cRow) * K + cGrp * 8;

    auto issue = [&](int c, int buf) {
        uint32_t dA = sbase + (uint32_t)buf * STG_T;
        uint32_t dB = dA + STG_A;
        #pragma unroll
        for (int pass = 0; pass < 4; pass++) {
            int row = cRow + pass * 32;
            uint32_t off = (uint32_t)row * 128 + (uint32_t)((cGrp ^ (row & 7)) << 4);
            cp16(dA + off, Ag + (size_t)(pass * 32) * K + c * 64);
            cp16(dB + off, Bg + (size_t)(pass * 32) * K + c * 64);
        }
        asm volatile("cp.async.commit_group;" ::: "memory");
    };

    // ldmatrix lane addressing (row part fixed across k-steps)
    int lr = lane & 7;
    int lh = (lane >> 3) & 1;          // m/n high-8 select
    uint32_t lk = (uint32_t)(lane >> 4);  // k-half select
    uint32_t aRowOff[4], aXor[4];
    #pragma unroll
    for (int mi = 0; mi < 4; mi++) {
        int row = warpM * 64 + mi * 16 + lr + lh * 8;
        aRowOff[mi] = (uint32_t)row * 128;
        aXor[mi] = (uint32_t)(row & 7);
    }
    uint32_t bRowOff[2], bXor[2];
    #pragma unroll
    for (int p = 0; p < 2; p++) {
        int row = warpN * 32 + p * 16 + lr + lh * 8;
        bRowOff[p] = (uint32_t)row * 128;
        bXor[p] = (uint32_t)(row & 7);
    }

    float acc[4][4][4];
    #pragma unroll
    for (int mi = 0; mi < 4; mi++)
        #pragma unroll
        for (int ni = 0; ni < 4; ni++)
            #pragma unroll
            for (int r = 0; r < 4; r++) acc[mi][ni][r] = 0.0f;

    int nc = K / 64;
    issue(0, 0);
    if (nc > 1) issue(1, 1);

    for (int c = 0; c < nc; c++) {
        if (c + 1 < nc)
            asm volatile("cp.async.wait_group 1;" ::: "memory");
        else
            asm volatile("cp.async.wait_group 0;" ::: "memory");
        __syncthreads();

        uint32_t sA = sbase + (uint32_t)(c & 1) * STG_T;
        uint32_t sB = sA + STG_A;

        #pragma unroll
        for (int ks = 0; ks < 4; ks++) {
            uint32_t kg = (uint32_t)(ks * 2) + lk;
            uint32_t afr[4][4], breg[2][4];
            #pragma unroll
            for (int mi = 0; mi < 4; mi++)
                ldsm4(afr[mi], sA + aRowOff[mi] + ((kg ^ aXor[mi]) << 4));
            #pragma unroll
            for (int p = 0; p < 2; p++)
                ldsm4(breg[p], sB + bRowOff[p] + ((kg ^ bXor[p]) << 4));
            #pragma unroll
            for (int mi = 0; mi < 4; mi++) {
                #pragma unroll
                for (int p = 0; p < 2; p++) {
                    uint32_t b0[2] = {breg[p][0], breg[p][2]};
                    uint32_t b1[2] = {breg[p][1], breg[p][3]};
                    mma_f16(acc[mi][2 * p], afr[mi], b0);
                    mma_f16(acc[mi][2 * p + 1], afr[mi], b1);
                }
            }
        }
        __syncthreads();
        if (c + 2 < nc) issue(c + 2, c & 1);
    }

    // epilogue
    #pragma unroll
    for (int mi = 0; mi < 4; mi++) {
        #pragma unroll
        for (int ni = 0; ni < 4; ni++) {
            int rA = row0 + warpM * 64 + mi * 16 + g;
            int cA = col0 + warpN * 32 + ni * 8 + tg * 2;
            float b0 = bias[cA], b1 = bias[cA + 1];
            #pragma unroll
            for (int half = 0; half < 2; half++) {
                int r = rA + half * 8;
                float o0 = acc[mi][ni][half * 2 + 0] + b0;
                float o1 = acc[mi][ni][half * 2 + 1] + b1;
                size_t idx = (size_t)r * N + cA;
                if (MODE == 1) {
                    const float2 rr = *(const float2*)&Rres[idx];
                    o0 += rr.x; o1 += rr.y;
                }
                if (MODE == 2) {
                    o0 = 0.5f * o0 * (1.0f + erff(o0 * 0.70710678118654752f));
                    o1 = 0.5f * o1 * (1.0f + erff(o1 * 0.70710678118654752f));
                }
                if (OUTH) {
                    *(__half2*)((__half*)Cout + idx) = __floats2half2_rn(o0, o1);
                } else {
                    *(float2*)((float*)Cout + idx) = make_float2(o0, o1);
                }
            }
        }
    }
}

// ---------------- flash attention with fp16 mma ----------------
#define KS_STR 72
#define VT_STR 264
#define ATT_SMEM ((256 * KS_STR + HS * VT_STR) * 2)   // 70656 bytes

__global__ __launch_bounds__(256) void attn_mma(const __half* __restrict__ qkv,
                                                __half* __restrict__ o) {
    extern __shared__ __align__(16) __half smh[];
    __half* Ks = smh;                      // [256][KS_STR]
    __half* Vt = smh + 256 * KS_STR;       // [64][VT_STR]
    int idx = blockIdx.x;
    int qt = idx & 1;
    int h = (idx >> 1) % HH;
    int b = idx / (2 * HH);
    size_t base = (size_t)b * TT * NQKV + (size_t)h * HS;
    int tid = threadIdx.x;
    int wid = tid >> 5, lane = tid & 31;
    int g = lane >> 2, tg = lane & 3;

    int nkeys = qt ? 256 : 128;
    for (int i = tid; i < nkeys * 8; i += 256) {
        int row = i >> 3, seg = i & 7;
        *(float4*)&Ks[row * KS_STR + seg * 8] =
            *(const float4*)&qkv[base + CC + (size_t)row * NQKV + seg * 8];
    }
    for (int k = wid; k < nkeys; k += 8) {
        __half2 v2 = *(const __half2*)&qkv[base + 2 * CC + (size_t)k * NQKV + 2 * lane];
        Vt[(2 * lane) * VT_STR + k] = __low2half(v2);
        Vt[(2 * lane + 1) * VT_STR + k] = __high2half(v2);
    }
    __syncthreads();

    int qbase = qt * 128 + wid * 16;
    uint32_t qf[4][4];
    const __half* qp = &qkv[base + (size_t)(qt * 128 + wid * 16) * NQKV];
    #pragma unroll
    for (int ks = 0; ks < 4; ks++) {
        int d0 = ks * 16;
        qf[ks][0] = *(const uint32_t*)&qp[(size_t)g * NQKV + d0 + 2 * tg];
        qf[ks][1] = *(const uint32_t*)&qp[(size_t)(g + 8) * NQKV + d0 + 2 * tg];
        qf[ks][2] = *(const uint32_t*)&qp[(size_t)g * NQKV + d0 + 8 + 2 * tg];
        qf[ks][3] = *(const uint32_t*)&qp[(size_t)(g + 8) * NQKV + d0 + 8 + 2 * tg];
    }

    float Oa[8][4];
    #pragma unroll
    for (int nb = 0; nb < 8; nb++)
        #pragma unroll
        for (int j = 0; j < 4; j++) Oa[nb][j] = 0.0f;
    float m0 = -1e30f, m1 = -1e30f, l0 = 0.0f, l1 = 0.0f;

    int ktmax = (qbase + 15) >> 6;
    for (int kt = 0; kt <= ktmax; kt++) {
        float S[8][4];
        #pragma unroll
        for (int nb = 0; nb < 8; nb++)
            #pragma unroll
            for (int j = 0; j < 4; j++) S[nb][j] = 0.0f;

        #pragma unroll
        for (int nb = 0; nb < 8; nb++) {
            int krow = (kt * 64 + nb * 8 + g) * KS_STR;
            #pragma unroll
            for (int ks = 0; ks < 4; ks++) {
                uint32_t bf[2];
                bf[0] = *(const uint32_t*)&Ks[krow + ks * 16 + 2 * tg];
                bf[1] = *(const uint32_t*)&Ks[krow + ks * 16 + 8 + 2 * tg];
                mma_f16(S[nb], qf[ks], bf);
            }
        }
        #pragma unroll
        for (int nb = 0; nb < 8; nb++)
            #pragma unroll
            for (int j = 0; j < 4; j++) S[nb][j] *= 0.125f;
        if (kt == ktmax) {
            int r0 = qbase + g, r1 = r0 + 8;
            #pragma unroll
            for (int nb = 0; nb < 8; nb++) {
                int col = kt * 64 + nb * 8 + 2 * tg;
                if (col > r0)     S[nb][0] = -1e30f;
                if (col + 1 > r0) S[nb][1] = -1e30f;
                if (col > r1)     S[nb][2] = -1e30f;
                if (col + 1 > r1) S[nb][3] = -1e30f;
            }
        }
        float tm0 = -1e30f, tm1 = -1e30f;
        #pragma unroll
        for (int nb = 0; nb < 8; nb++) {
            tm0 = fmaxf(tm0, fmaxf(S[nb][0], S[nb][1]));
            tm1 = fmaxf(tm1, fmaxf(S[nb][2], S[nb][3]));
        }
        tm0 = fmaxf(tm0, __shfl_xor_sync(0xffffffffu, tm0, 1));
        tm0 = fmaxf(tm0, __shfl_xor_sync(0xffffffffu, tm0, 2));
        tm1 = fmaxf(tm1, __shfl_xor_sync(0xffffffffu, tm1, 1));
        tm1 = fmaxf(tm1, __shfl_xor_sync(0xffffffffu, tm1, 2));
        float mn0 = fmaxf(m0, tm0), mn1 = fmaxf(m1, tm1);
        float sc0 = __expf(m0 - mn0), sc1 = __expf(m1 - mn1);
        float ts0 = 0.0f, ts1 = 0.0f;
        #pragma unroll
        for (int nb = 0; nb < 8; nb++) {
            S[nb][0] = __expf(S[nb][0] - mn0);
            S[nb][1] = __expf(S[nb][1] - mn0);
            S[nb][2] = __expf(S[nb][2] - mn1);
            S[nb][3] = __expf(S[nb][3] - mn1);
            ts0 += S[nb][0] + S[nb][1];
            ts1 += S[nb][2] + S[nb][3];
        }
        ts0 += __shfl_xor_sync(0xffffffffu, ts0, 1);
        ts0 += __shfl_xor_sync(0xffffffffu, ts0, 2);
        ts1 += __shfl_xor_sync(0xffffffffu, ts1, 1);
        ts1 += __shfl_xor_sync(0xffffffffu, ts1, 2);
        l0 = l0 * sc0 + ts0;
        l1 = l1 * sc1 + ts1;
        m0 = mn0; m1 = mn1;
        #pragma unroll
        for (int nb = 0; nb < 8; nb++) {
            Oa[nb][0] *= sc0; Oa[nb][1] *= sc0;
            Oa[nb][2] *= sc1; Oa[nb][3] *= sc1;
        }
        #pragma unroll
        for (int ks = 0; ks < 4; ks++) {
            uint32_t ap[4];
            ap[0] = h2u(__floats2half2_rn(S[2 * ks][0], S[2 * ks][1]));
            ap[1] = h2u(__floats2half2_rn(S[2 * ks][2], S[2 * ks][3]));
            ap[2] = h2u(__floats2half2_rn(S[2 * ks + 1][0], S[2 * ks + 1][1]));
            ap[3] = h2u(__floats2half2_rn(S[2 * ks + 1][2], S[2 * ks + 1][3]));
            int k0 = kt * 64 + ks * 16;
            #pragma unroll
            for (int nb = 0; nb < 8; nb++) {
                uint32_t bf[2];
                bf[0] = *(const uint32_t*)&Vt[(nb * 8 + g) * VT_STR + k0 + 2 * tg];
                bf[1] = *(const uint32_t*)&Vt[(nb * 8 + g) * VT_STR + k0 + 8 + 2 * tg];
                mma_f16(Oa[nb], ap, bf);
            }
        }
    }

    float inv0 = 1.0f / l0, inv1 = 1.0f / l1;
    __half* op = o + ((size_t)(b * TT + qt * 128 + wid * 16 + g) * CC + h * HS);
    __half* op1 = op + 8 * CC;
    #pragma unroll
    for (int nb = 0; nb < 8; nb++) {
        *(__half2*)&op[nb * 8 + 2 * tg]  = __floats2half2_rn(Oa[nb][0] * inv0, Oa[nb][1] * inv0);
        *(__half2*)&op1[nb * 8 + 2 * tg] = __floats2half2_rn(Oa[nb][2] * inv1, Oa[nb][3] * inv1);
    }
}

// ---------------- launch ----------------
extern "C" void kernel_launch(void* const* d_in, const int* in_sizes, int n_in,
                              void* d_out, int out_size) {
    const float* x     = (const float*)d_in[0];
    const float* ln1w  = (const float*)d_in[1];
    const float* ln1b  = (const float*)d_in[2];
    const float* Wq    = (const float*)d_in[3];
    const float* bq    = (const float*)d_in[4];
    const float* Wk    = (const float*)d_in[5];
    const float* bk    = (const float*)d_in[6];
    const float* Wv    = (const float*)d_in[7];
    const float* bv    = (const float*)d_in[8];
    const float* Wproj = (const float*)d_in[9];
    const float* bproj = (const float*)d_in[10];
    const float* ln2w  = (const float*)d_in[11];
    const float* ln2b  = (const float*)d_in[12];
    const float* W1    = (const float*)d_in[13];
    const float* b1    = (const float*)d_in[14];
    const float* W2    = (const float*)d_in[15];
    const float* b2    = (const float*)d_in[16];
    float* out = (float*)d_out;

    __half *h, *qkvh, *o, *f1, *wqkvT, *wprojT, *w1T, *w2T;
    float *x1, *bqkv;
    cudaGetSymbolAddress((void**)&h, g_h);
    cudaGetSymbolAddress((void**)&qkvh, g_qkvh);
    cudaGetSymbolAddress((void**)&o, g_o);
    cudaGetSymbolAddress((void**)&x1, g_x1);
    cudaGetSymbolAddress((void**)&f1, g_f1);
    cudaGetSymbolAddress((void**)&wqkvT, g_WqkvT);
    cudaGetSymbolAddress((void**)&wprojT, g_WprojT);
    cudaGetSymbolAddress((void**)&w1T, g_W1T);
    cudaGetSymbolAddress((void**)&w2T, g_W2T);
    cudaGetSymbolAddress((void**)&bqkv, g_bqkv);

    cudaFuncSetAttribute(attn_mma, cudaFuncAttributeMaxDynamicSharedMemorySize, ATT_SMEM);
    cudaFuncSetAttribute(mma_gemm16<0, 1>, cudaFuncAttributeMaxDynamicSharedMemorySize, SMEM_TOTAL_G);
    cudaFuncSetAttribute(mma_gemm16<1, 0>, cudaFuncAttributeMaxDynamicSharedMemorySize, SMEM_TOTAL_G);
    cudaFuncSetAttribute(mma_gemm16<2, 1>, cudaFuncAttributeMaxDynamicSharedMemorySize, SMEM_TOTAL_G);

    // weight packing (fp16, transposed to [N,K])
    pack_qkv_t<<<(NQKV * CC + 255) / 256, 256>>>(Wq, Wk, Wv, bq, bk, bv);
    transpose_w<<<(CC * CC + 255) / 256, 256>>>(Wproj, wprojT, CC, CC);
    transpose_w<<<(CF * CC + 255) / 256, 256>>>(W1, w1T, CC, CF);
    transpose_w<<<(CC * CF + 255) / 256, 256>>>(W2, w2T, CF, CC);

    // LN1 (-> half)
    ln_kernel<<<MM, 128>>>(x, ln1w, ln1b, h);
    // QKV GEMM (half out)
    mma_gemm16<0, 1><<<dim3(NQKV / 128, MM / 128), 256, SMEM_TOTAL_G>>>(h, wqkvT, bqkv, nullptr, qkvh, MM, NQKV, CC);
    // flash attention (half in/out)
    attn_mma<<<BB * HH * 2, 256, ATT_SMEM>>>(qkvh, o);
    // proj + residual (-> f32 x1)
    mma_gemm16<1, 0><<<dim3(CC / 128, MM / 128), 256, SMEM_TOTAL_G>>>(o, wprojT, bproj, x, x1, MM, CC, CC);
    // LN2 (-> half)
    ln_kernel<<<MM, 128>>>(x1, ln2w, ln2b, h);
    // FFN1 + GELU (-> half f1)
    mma_gemm16<2, 1><<<dim3(CF / 128, MM / 128), 256, SMEM_TOTAL_G>>>(h, w1T, b1, nullptr, f1, MM, CF, CC);
    // FFN2 + residual (-> f32 out)
    mma_gemm16<1, 0><<<dim3(CC / 128, MM / 128), 256, SMEM_TOTAL_G>>>(f1, w2T, b2, x1, out, MM, CC, CF);
}

// round 8
// speedup vs baseline: 6.4210x; 1.0415x over previous
#include <cuda_runtime.h>
#include <cuda_fp16.h>
#include <math.h>
#include <cstdint>

// Problem constants
#define BB 64
#define TT 256
#define CC 384
#define HH 6
#define HS 64
#define MM (BB * TT)          // 16384
#define NQKV (3 * CC)         // 1152
#define CF (4 * CC)           // 1536

// ---------------- scratch (static __device__, no allocs) ----------------
__device__ __half g_h[MM * CC];       // ln output (half, GEMM A input)
__device__ __half g_qkvh[MM * NQKV];  // packed Q|K|V (half)
__device__ __half g_o[MM * CC];       // attention output (half)
__device__ float  g_x1[MM * CC];      // first residual (f32)
__device__ __half g_f1[MM * CF];      // FFN hidden (half)
// transposed (N-major, K-contig) fp16 weights
__device__ __half g_WqkvT[NQKV * CC];
__device__ __half g_WprojT[CC * CC];
__device__ __half g_W1T[CF * CC];
__device__ __half g_W2T[CC * CF];
__device__ float  g_bqkv[NQKV];

__device__ __forceinline__ uint32_t smem_u32(const void* p) {
    uint32_t a;
    asm("{ .reg .u64 t; cvta.to.shared.u64 t, %1; cvt.u32.u64 %0, t; }" : "=r"(a) : "l"(p));
    return a;
}

// ---------------- fused weight pack: all 4 matrices + qkv bias, one kernel ----------
#define N_QKVW (NQKV * CC)            // 442368
#define N_PROJ (CC * CC)              // 147456
#define N_W1   (CC * CF)              // 589824
#define N_W2   (CF * CC)              // 589824
#define OFF_PROJ N_QKVW
#define OFF_W1   (OFF_PROJ + N_PROJ)
#define OFF_W2   (OFF_W1 + N_W1)
#define N_PACK   (OFF_W2 + N_W2)      // 1769472

__global__ void pack_all(const float* __restrict__ Wq, const float* __restrict__ Wk,
                         const float* __restrict__ Wv, const float* __restrict__ bq,
                         const float* __restrict__ bk, const float* __restrict__ bv,
                         const float* __restrict__ Wproj, const float* __restrict__ W1,
                         const float* __restrict__ W2) {
    int i = blockIdx.x * 256 + threadIdx.x;
    if (i < N_QKVW) {
        int n = i / CC, k = i % CC;
        int s2 = n / CC;                 // 0,1,2 selects Q/K/V
        int nn = n % CC;                 // h*HS + d
        const float* src = (s2 == 0) ? Wq : (s2 == 1) ? Wk : Wv;
        g_WqkvT[i] = __float2half_rn(src[(nn / HS) * (CC * HS) + k * HS + (nn % HS)]);
    } else if (i < OFF_W1) {
        int j = i - OFF_PROJ;
        int n = j / CC, k = j % CC;
        g_WprojT[j] = __float2half_rn(Wproj[(size_t)k * CC + n]);
    } else if (i < OFF_W2) {
        int j = i - OFF_W1;
        int n = j / CC, k = j % CC;      // dst [CF rows, K=CC]
        g_W1T[j] = __float2half_rn(W1[(size_t)k * CF + n]);
    } else if (i < N_PACK) {
        int j = i - OFF_W2;
        int n = j / CF, k = j % CF;      // dst [CC rows, K=CF]
        g_W2T[j] = __float2half_rn(W2[(size_t)k * CC + n]);
    }
    if (i < NQKV) {
        int s2 = i / CC;
        int nn = i % CC;
        const float* sb = (s2 == 0) ? bq : (s2 == 1) ? bk : bv;
        g_bqkv[i] = sb[nn];
    }
}

// ---------------- LayerNorm (f32 in, half out) ----------------
__global__ __launch_bounds__(128) void ln_kernel(const float* __restrict__ x,
                                                 const float* __restrict__ w,
                                                 const float* __restrict__ b,
                                                 __half* __restrict__ y) {
    int row = blockIdx.x;
    const float* xr = x + (size_t)row * CC;
    int tid = threadIdx.x;
    float v0 = xr[tid], v1 = xr[tid + 128], v2 = xr[tid + 256];
    float s = v0 + v1 + v2;
    float ss = v0 * v0 + v1 * v1 + v2 * v2;
    __shared__ float red[8];
    #pragma unroll
    for (int o = 16; o > 0; o >>= 1) {
        s += __shfl_down_sync(0xffffffffu, s, o);
        ss += __shfl_down_sync(0xffffffffu, ss, o);
    }
    int wid = tid >> 5, lid = tid & 31;
    if (lid == 0) { red[wid] = s; red[4 + wid] = ss; }
    __syncthreads();
    if (tid == 0) {
        float S = red[0] + red[1] + red[2] + red[3];
        float SS = red[4] + red[5] + red[6] + red[7];
        float mean = S * (1.0f / CC);
        float var = SS * (1.0f / CC) - mean * mean;
        red[0] = mean;
        red[1] = rsqrtf(var + 1e-5f);
    }
    __syncthreads();
    float mean = red[0], inv = red[1];
    __half* yr = y + (size_t)row * CC;
    yr[tid]       = __float2half_rn((v0 - mean) * inv * w[tid]       + b[tid]);
    yr[tid + 128] = __float2half_rn((v1 - mean) * inv * w[tid + 128] + b[tid + 128]);
    yr[tid + 256] = __float2half_rn((v2 - mean) * inv * w[tid + 256] + b[tid + 256]);
}

// ---------------- fp16 mma helpers ----------------
__device__ __forceinline__ void mma_f16(float* c, const uint32_t* a, const uint32_t* b) {
    asm volatile(
        "mma.sync.aligned.m16n8k16.row.col.f32.f16.f16.f32 "
        "{%0,%1,%2,%3}, {%4,%5,%6,%7}, {%8,%9}, {%0,%1,%2,%3};"
        : "+f"(c[0]), "+f"(c[1]), "+f"(c[2]), "+f"(c[3])
        : "r"(a[0]), "r"(a[1]), "r"(a[2]), "r"(a[3]), "r"(b[0]), "r"(b[1]));
}

__device__ __forceinline__ void cp16(uint32_t dst, const void* src) {
    asm volatile("cp.async.cg.shared.global [%0], [%1], 16;" :: "r"(dst), "l"(src));
}
__device__ __forceinline__ uint32_t h2u(__half2 v) {
    return *(uint32_t*)&v;
}
__device__ __forceinline__ void ldsm4(uint32_t* r, uint32_t addr) {
    asm volatile("ldmatrix.sync.aligned.m8n8.x4.shared.b16 {%0,%1,%2,%3}, [%4];"
        : "=r"(r[0]), "=r"(r[1]), "=r"(r[2]), "=r"(r[3]) : "r"(addr));
}

// ---------------- fp16 mma.sync GEMM: 3-stage ring, 1 sync/chunk, 2 CTA/SM ---------
// C[M,N] = A[M,K] @ Bt[N,K]^T + bias ; MODE 0 bias, 1 bias+residual, 2 gelu(bias)
// CTA tile 128x128, 8 warps (2M x 4N), warp 64x32, K-chunk 64 halves (128B rows).
// Smem: row = 128B = 8 x 16B groups; group swizzled by XOR(row&7). No padding.
#define STG_A 16384                    // 128 rows * 128B
#define STG_T 32768                    // A + B per stage
#define SMEM_TOTAL_G (3 * STG_T)       // 98304 (3 stages)

template <int MODE, int OUTH>
__global__ __launch_bounds__(256, 2) void mma_gemm16(const __half* __restrict__ A,
                                                     const __half* __restrict__ Bt,
                                                     const float* __restrict__ bias,
                                                     const float* __restrict__ Rres,
                                                     void* __restrict__ Cout,
                                                     int M, int N, int K) {
    extern __shared__ __align__(16) char smem[];
    int tid = threadIdx.x;
    int lane = tid & 31, wid = tid >> 5;
    int warpM = wid & 1, warpN = wid >> 1;
    int g = lane >> 2, tg = lane & 3;
    int row0 = blockIdx.y * 128, col0 = blockIdx.x * 128;

    uint32_t sbase = smem_u32(smem);

    // cp.async mapping: 8 threads per row, 16B per thread, 4 passes (32 rows each)
    int cRow = tid >> 3;               // 0..31
    int cGrp = tid & 7;                // 16B group
    const __half* Ag = A + (size_t)(row0 + cRow) * K + cGrp * 8;
    const __half* Bg = Bt + (size_t)(col0 + cRow) * K + cGrp * 8;

    auto issue = [&](int c, int buf) {
        uint32_t dA = sbase + (uint32_t)buf * STG_T;
        uint32_t dB = dA + STG_A;
        #pragma unroll
        for (int pass = 0; pass < 4; pass++) {
            int row = cRow + pass * 32;
            uint32_t off = (uint32_t)row * 128 + (uint32_t)((cGrp ^ (row & 7)) << 4);
            cp16(dA + off, Ag + (size_t)(pass * 32) * K + c * 64);
            cp16(dB + off, Bg + (size_t)(pass * 32) * K + c * 64);
        }
        asm volatile("cp.async.commit_group;" ::: "memory");
    };

    // ldmatrix lane addressing (row part fixed across k-steps)
    int lr = lane & 7;
    int lh = (lane >> 3) & 1;          // m/n high-8 select
    uint32_t lk = (uint32_t)(lane >> 4);  // k-half select
    uint32_t aRowOff[4], aXor[4];
    #pragma unroll
    for (int mi = 0; mi < 4; mi++) {
        int row = warpM * 64 + mi * 16 + lr + lh * 8;
        aRowOff[mi] = (uint32_t)row * 128;
        aXor[mi] = (uint32_t)(row & 7);
    }
    uint32_t bRowOff[2], bXor[2];
    #pragma unroll
    for (int p = 0; p < 2; p++) {
        int row = warpN * 32 + p * 16 + lr + lh * 8;
        bRowOff[p] = (uint32_t)row * 128;
        bXor[p] = (uint32_t)(row & 7);
    }

    float acc[4][4][4];
    #pragma unroll
    for (int mi = 0; mi < 4; mi++)
        #pragma unroll
        for (int ni = 0; ni < 4; ni++)
            #pragma unroll
            for (int r = 0; r < 4; r++) acc[mi][ni][r] = 0.0f;

    int nc = K / 64;
    issue(0, 0);
    if (nc > 1) issue(1, 1);
    if (nc > 2) issue(2, 2);

    for (int c = 0; c < nc; c++) {
        if (c + 1 < nc)
            asm volatile("cp.async.wait_group 1;" ::: "memory");
        else
            asm volatile("cp.async.wait_group 0;" ::: "memory");
        __syncthreads();
        // all warps finished chunk c-1's buffer -> safe to refill it with chunk c+2
        if (c >= 1 && c + 2 < nc) issue(c + 2, (c + 2) % 3);

        uint32_t sA = sbase + (uint32_t)(c % 3) * STG_T;
        uint32_t sB = sA + STG_A;

        #pragma unroll
        for (int ks = 0; ks < 4; ks++) {
            uint32_t kg = (uint32_t)(ks * 2) + lk;
            uint32_t afr[4][4], breg[2][4];
            #pragma unroll
            for (int mi = 0; mi < 4; mi++)
                ldsm4(afr[mi], sA + aRowOff[mi] + ((kg ^ aXor[mi]) << 4));
            #pragma unroll
            for (int p = 0; p < 2; p++)
                ldsm4(breg[p], sB + bRowOff[p] + ((kg ^ bXor[p]) << 4));
            #pragma unroll
            for (int mi = 0; mi < 4; mi++) {
                #pragma unroll
                for (int p = 0; p < 2; p++) {
                    uint32_t b0[2] = {breg[p][0], breg[p][2]};
                    uint32_t b1[2] = {breg[p][1], breg[p][3]};
                    mma_f16(acc[mi][2 * p], afr[mi], b0);
                    mma_f16(acc[mi][2 * p + 1], afr[mi], b1);
                }
            }
        }
        // no second barrier: next iteration's wait+sync protects the ring
    }

    // epilogue
    #pragma unroll
    for (int mi = 0; mi < 4; mi++) {
        #pragma unroll
        for (int ni = 0; ni < 4; ni++) {
            int rA = row0 + warpM * 64 + mi * 16 + g;
            int cA = col0 + warpN * 32 + ni * 8 + tg * 2;
            float b0 = bias[cA], b1 = bias[cA + 1];
            #pragma unroll
            for (int half = 0; half < 2; half++) {
                int r = rA + half * 8;
                float o0 = acc[mi][ni][half * 2 + 0] + b0;
                float o1 = acc[mi][ni][half * 2 + 1] + b1;
                size_t idx = (size_t)r * N + cA;
                if (MODE == 1) {
                    const float2 rr = *(const float2*)&Rres[idx];
                    o0 += rr.x; o1 += rr.y;
                }
                if (MODE == 2) {
                    o0 = 0.5f * o0 * (1.0f + erff(o0 * 0.70710678118654752f));
                    o1 = 0.5f * o1 * (1.0f + erff(o1 * 0.70710678118654752f));
                }
                if (OUTH) {
                    *(__half2*)((__half*)Cout + idx) = __floats2half2_rn(o0, o1);
                } else {
                    *(float2*)((float*)Cout + idx) = make_float2(o0, o1);
                }
            }
        }
    }
}

// ---------------- flash attention with fp16 mma ----------------
#define KS_STR 72
#define VT_STR 264
#define ATT_SMEM ((256 * KS_STR + HS * VT_STR) * 2)   // 70656 bytes

__global__ __launch_bounds__(256) void attn_mma(const __half* __restrict__ qkv,
                                                __half* __restrict__ o) {
    extern __shared__ __align__(16) __half smh[];
    __half* Ks = smh;                      // [256][KS_STR]
    __half* Vt = smh + 256 * KS_STR;       // [64][VT_STR]
    int idx = blockIdx.x;
    int qt = idx & 1;
    int h = (idx >> 1) % HH;
    int b = idx / (2 * HH);
    size_t base = (size_t)b * TT * NQKV + (size_t)h * HS;
    int tid = threadIdx.x;
    int wid = tid >> 5, lane = tid & 31;
    int g = lane >> 2, tg = lane & 3;

    int nkeys = qt ? 256 : 128;
    for (int i = tid; i < nkeys * 8; i += 256) {
        int row = i >> 3, seg = i & 7;
        *(float4*)&Ks[row * KS_STR + seg * 8] =
            *(const float4*)&qkv[base + CC + (size_t)row * NQKV + seg * 8];
    }
    for (int k = wid; k < nkeys; k += 8) {
        __half2 v2 = *(const __half2*)&qkv[base + 2 * CC + (size_t)k * NQKV + 2 * lane];
        Vt[(2 * lane) * VT_STR + k] = __low2half(v2);
        Vt[(2 * lane + 1) * VT_STR + k] = __high2half(v2);
    }
    __syncthreads();

    int qbase = qt * 128 + wid * 16;
    uint32_t qf[4][4];
    const __half* qp = &qkv[base + (size_t)(qt * 128 + wid * 16) * NQKV];
    #pragma unroll
    for (int ks = 0; ks < 4; ks++) {
        int d0 = ks * 16;
        qf[ks][0] = *(const uint32_t*)&qp[(size_t)g * NQKV + d0 + 2 * tg];
        qf[ks][1] = *(const uint32_t*)&qp[(size_t)(g + 8) * NQKV + d0 + 2 * tg];
        qf[ks][2] = *(const uint32_t*)&qp[(size_t)g * NQKV + d0 + 8 + 2 * tg];
        qf[ks][3] = *(const uint32_t*)&qp[(size_t)(g + 8) * NQKV + d0 + 8 + 2 * tg];
    }

    float Oa[8][4];
    #pragma unroll
    for (int nb = 0; nb < 8; nb++)
        #pragma unroll
        for (int j = 0; j < 4; j++) Oa[nb][j] = 0.0f;
    float m0 = -1e30f, m1 = -1e30f, l0 = 0.0f, l1 = 0.0f;

    int ktmax = (qbase + 15) >> 6;
    for (int kt = 0; kt <= ktmax; kt++) {
        float S[8][4];
        #pragma unroll
        for (int nb = 0; nb < 8; nb++)
            #pragma unroll
            for (int j = 0; j < 4; j++) S[nb][j] = 0.0f;

        #pragma unroll
        for (int nb = 0; nb < 8; nb++) {
            int krow = (kt * 64 + nb * 8 + g) * KS_STR;
            #pragma unroll
            for (int ks = 0; ks < 4; ks++) {
                uint32_t bf[2];
                bf[0] = *(const uint32_t*)&Ks[krow + ks * 16 + 2 * tg];
                bf[1] = *(const uint32_t*)&Ks[krow + ks * 16 + 8 + 2 * tg];
                mma_f16(S[nb], qf[ks], bf);
            }
        }
        #pragma unroll
        for (int nb = 0; nb < 8; nb++)
            #pragma unroll
            for (int j = 0; j < 4; j++) S[nb][j] *= 0.125f;
        if (kt == ktmax) {
            int r0 = qbase + g, r1 = r0 + 8;
            #pragma unroll
            for (int nb = 0; nb < 8; nb++) {
                int col = kt * 64 + nb * 8 + 2 * tg;
                if (col > r0)     S[nb][0] = -1e30f;
                if (col + 1 > r0) S[nb][1] = -1e30f;
                if (col > r1)     S[nb][2] = -1e30f;
                if (col + 1 > r1) S[nb][3] = -1e30f;
            }
        }
        float tm0 = -1e30f, tm1 = -1e30f;
        #pragma unroll
        for (int nb = 0; nb < 8; nb++) {
            tm0 = fmaxf(tm0, fmaxf(S[nb][0], S[nb][1]));
            tm1 = fmaxf(tm1, fmaxf(S[nb][2], S[nb][3]));
        }
        tm0 = fmaxf(tm0, __shfl_xor_sync(0xffffffffu, tm0, 1));
        tm0 = fmaxf(tm0, __shfl_xor_sync(0xffffffffu, tm0, 2));
        tm1 = fmaxf(tm1, __shfl_xor_sync(0xffffffffu, tm1, 1));
        tm1 = fmaxf(tm1, __shfl_xor_sync(0xffffffffu, tm1, 2));
        float mn0 = fmaxf(m0, tm0), mn1 = fmaxf(m1, tm1);
        float sc0 = __expf(m0 - mn0), sc1 = __expf(m1 - mn1);
        float ts0 = 0.0f, ts1 = 0.0f;
        #pragma unroll
        for (int nb = 0; nb < 8; nb++) {
            S[nb][0] = __expf(S[nb][0] - mn0);
            S[nb][1] = __expf(S[nb][1] - mn0);
            S[nb][2] = __expf(S[nb][2] - mn1);
            S[nb][3] = __expf(S[nb][3] - mn1);
            ts0 += S[nb][0] + S[nb][1];
            ts1 += S[nb][2] + S[nb][3];
        }
        ts0 += __shfl_xor_sync(0xffffffffu, ts0, 1);
        ts0 += __shfl_xor_sync(0xffffffffu, ts0, 2);
        ts1 += __shfl_xor_sync(0xffffffffu, ts1, 1);
        ts1 += __shfl_xor_sync(0xffffffffu, ts1, 2);
        l0 = l0 * sc0 + ts0;
        l1 = l1 * sc1 + ts1;
        m0 = mn0; m1 = mn1;
        #pragma unroll
        for (int nb = 0; nb < 8; nb++) {
            Oa[nb][0] *= sc0; Oa[nb][1] *= sc0;
            Oa[nb][2] *= sc1; Oa[nb][3] *= sc1;
        }
        #pragma unroll
        for (int ks = 0; ks < 4; ks++) {
            uint32_t ap[4];
            ap[0] = h2u(__floats2half2_rn(S[2 * ks][0], S[2 * ks][1]));
            ap[1] = h2u(__floats2half2_rn(S[2 * ks][2], S[2 * ks][3]));
            ap[2] = h2u(__floats2half2_rn(S[2 * ks + 1][0], S[2 * ks + 1][1]));
            ap[3] = h2u(__floats2half2_rn(S[2 * ks + 1][2], S[2 * ks + 1][3]));
            int k0 = kt * 64 + ks * 16;
            #pragma unroll
            for (int nb = 0; nb < 8; nb++) {
                uint32_t bf[2];
                bf[0] = *(const uint32_t*)&Vt[(nb * 8 + g) * VT_STR + k0 + 2 * tg];
                bf[1] = *(const uint32_t*)&Vt[(nb * 8 + g) * VT_STR + k0 + 8 + 2 * tg];
                mma_f16(Oa[nb], ap, bf);
            }
        }
    }

    float inv0 = 1.0f / l0, inv1 = 1.0f / l1;
    __half* op = o + ((size_t)(b * TT + qt * 128 + wid * 16 + g) * CC + h * HS);
    __half* op1 = op + 8 * CC;
    #pragma unroll
    for (int nb = 0; nb < 8; nb++) {
        *(__half2*)&op[nb * 8 + 2 * tg]  = __floats2half2_rn(Oa[nb][0] * inv0, Oa[nb][1] * inv0);
        *(__half2*)&op1[nb * 8 + 2 * tg] = __floats2half2_rn(Oa[nb][2] * inv1, Oa[nb][3] * inv1);
    }
}

// ---------------- launch ----------------
extern "C" void kernel_launch(void* const* d_in, const int* in_sizes, int n_in,
                              void* d_out, int out_size) {
    const float* x     = (const float*)d_in[0];
    const float* ln1w  = (const float*)d_in[1];
    const float* ln1b  = (const float*)d_in[2];
    const float* Wq    = (const float*)d_in[3];
    const float* bq    = (const float*)d_in[4];
    const float* Wk    = (const float*)d_in[5];
    const float* bk    = (const float*)d_in[6];
    const float* Wv    = (const float*)d_in[7];
    const float* bv    = (const float*)d_in[8];
    const float* Wproj = (const float*)d_in[9];
    const float* bproj = (const float*)d_in[10];
    const float* ln2w  = (const float*)d_in[11];
    const float* ln2b  = (const float*)d_in[12];
    const float* W1    = (const float*)d_in[13];
    const float* b1    = (const float*)d_in[14];
    const float* W2    = (const float*)d_in[15];
    const float* b2    = (const float*)d_in[16];
    float* out = (float*)d_out;

    __half *h, *qkvh, *o, *f1, *wqkvT, *wprojT, *w1T, *w2T;
    float *x1, *bqkv;
    cudaGetSymbolAddress((void**)&h, g_h);
    cudaGetSymbolAddress((void**)&qkvh, g_qkvh);
    cudaGetSymbolAddress((void**)&o, g_o);
    cudaGetSymbolAddress((void**)&x1, g_x1);
    cudaGetSymbolAddress((void**)&f1, g_f1);
    cudaGetSymbolAddress((void**)&wqkvT, g_WqkvT);
    cudaGetSymbolAddress((void**)&wprojT, g_WprojT);
    cudaGetSymbolAddress((void**)&w1T, g_W1T);
    cudaGetSymbolAddress((void**)&w2T, g_W2T);
    cudaGetSymbolAddress((void**)&bqkv, g_bqkv);

    cudaFuncSetAttribute(attn_mma, cudaFuncAttributeMaxDynamicSharedMemorySize, ATT_SMEM);
    cudaFuncSetAttribute(mma_gemm16<0, 1>, cudaFuncAttributeMaxDynamicSharedMemorySize, SMEM_TOTAL_G);
    cudaFuncSetAttribute(mma_gemm16<1, 0>, cudaFuncAttributeMaxDynamicSharedMemorySize, SMEM_TOTAL_G);
    cudaFuncSetAttribute(mma_gemm16<2, 1>, cudaFuncAttributeMaxDynamicSharedMemorySize, SMEM_TOTAL_G);

    // fused weight packing (fp16, transposed to [N,K])
    pack_all<<<(N_PACK + 255) / 256, 256>>>(Wq, Wk, Wv, bq, bk, bv, Wproj, W1, W2);

    // LN1 (-> half)
    ln_kernel<<<MM, 128>>>(x, ln1w, ln1b, h);
    // QKV GEMM (half out)
    mma_gemm16<0, 1><<<dim3(NQKV / 128, MM / 128), 256, SMEM_TOTAL_G>>>(h, wqkvT, bqkv, nullptr, qkvh, MM, NQKV, CC);
    // flash attention (half in/out)
    attn_mma<<<BB * HH * 2, 256, ATT_SMEM>>>(qkvh, o);
    // proj + residual (-> f32 x1)
    mma_gemm16<1, 0><<<dim3(CC / 128, MM / 128), 256, SMEM_TOTAL_G>>>(o, wprojT, bproj, x, x1, MM, CC, CC);
    // LN2 (-> half)
    ln_kernel<<<MM, 128>>>(x1, ln2w, ln2b, h);
    // FFN1 + GELU (-> half f1)
    mma_gemm16<2, 1><<<dim3(CF / 128, MM / 128), 256, SMEM_TOTAL_G>>>(h, w1T, b1, nullptr, f1, MM, CF, CC);
    // FFN2 + residual (-> f32 out)
    mma_gemm16<1, 0><<<dim3(CC / 128, MM / 128), 256, SMEM_TOTAL_G>>>(f1, w2T, b2, x1, out, MM, CC, CF);
}